// round 7
// baseline (speedup 1.0000x reference)
#include <cuda_runtime.h>
#include <cuda_bf16.h>
#include <cstdint>
#include <cstddef>

#define SEQ    2048
#define BATCH  2
#define DMODEL 1024
#define NHEADS 16
#define DHEAD  64
#define MROWS  (BATCH*SEQ)

// ---------------- scratch (device globals; allocation-free rule) ------------
__device__ __nv_bfloat16 g_Xh [(size_t)MROWS*DMODEL], g_Xl [(size_t)MROWS*DMODEL];
__device__ __nv_bfloat16 g_BTh[(size_t)DMODEL*DMODEL], g_BTl[(size_t)DMODEL*DMODEL];
__device__ __nv_bfloat16 g_Bmh[(size_t)DMODEL*DMODEL], g_Bml[(size_t)DMODEL*DMODEL];
__device__ __nv_bfloat16 g_XBqh[(size_t)MROWS*DMODEL], g_XBql[(size_t)MROWS*DMODEL];
__device__ __nv_bfloat16 g_XBkh[(size_t)MROWS*DMODEL], g_XBkl[(size_t)MROWS*DMODEL];
__device__ __nv_bfloat16 g_XBvh[(size_t)MROWS*DMODEL], g_XBvl[(size_t)MROWS*DMODEL];
__device__ __nv_bfloat16 g_AOh[(size_t)MROWS*DMODEL],  g_AOl[(size_t)MROWS*DMODEL];
__device__ __nv_bfloat16 g_O1h[(size_t)MROWS*DMODEL],  g_O1l[(size_t)MROWS*DMODEL];
__device__ float g_Q[(size_t)MROWS*DMODEL], g_K[(size_t)MROWS*DMODEL], g_V[(size_t)MROWS*DMODEL];

// ---------------------------------------------------------------------------
__device__ __forceinline__ uint32_t smem_u32(const void* p) {
    uint32_t a;
    asm("{ .reg .u64 t; cvta.to.shared.u64 t, %1; cvt.u32.u64 %0, t; }"
        : "=r"(a) : "l"(p));
    return a;
}

#define LDMX4(r0, r1, r2, r3, addr) \
    asm volatile("ldmatrix.sync.aligned.m8n8.x4.shared.b16 {%0,%1,%2,%3}, [%4];" \
                 : "=r"(r0), "=r"(r1), "=r"(r2), "=r"(r3) : "r"(addr))

#define LDMX4T(r0, r1, r2, r3, addr) \
    asm volatile("ldmatrix.sync.aligned.m8n8.x4.trans.shared.b16 {%0,%1,%2,%3}, [%4];" \
                 : "=r"(r0), "=r"(r1), "=r"(r2), "=r"(r3) : "r"(addr))

#define MMA16816_2(d, a, b0r, b1r) \
    asm volatile("mma.sync.aligned.m16n8k16.row.col.f32.bf16.bf16.f32 " \
                 "{%0,%1,%2,%3}, {%4,%5,%6,%7}, {%8,%9}, {%0,%1,%2,%3};" \
                 : "+f"((d)[0]), "+f"((d)[1]), "+f"((d)[2]), "+f"((d)[3]) \
                 : "r"((a)[0]), "r"((a)[1]), "r"((a)[2]), "r"((a)[3]), \
                   "r"(b0r), "r"(b1r))

#define CPASYNC16(dst, src) \
    asm volatile("cp.async.cg.shared.global [%0], [%1], 16;" \
                 :: "r"(dst), "l"(src))
#define CPCOMMIT()  asm volatile("cp.async.commit_group;" ::: "memory")
#define CPWAIT(n)   asm volatile("cp.async.wait_group %0;" :: "n"(n) : "memory")

// XOR swizzle: 16B chunk index ^= row-pair (64B rows, conflict-free ldmatrix)
__device__ __forceinline__ uint32_t swz(uint32_t o) {
    return o ^ (((o >> 7) & 3u) << 4);
}

__device__ __forceinline__ uint32_t packbf(float a, float b) {
    __nv_bfloat16 x = __float2bfloat16(a), y = __float2bfloat16(b);
    return (uint32_t)__bfloat16_as_ushort(x) | ((uint32_t)__bfloat16_as_ushort(y) << 16);
}

__device__ __forceinline__ void split_store(void* hp, void* lp, float4 v) {
    __nv_bfloat16 h0 = __float2bfloat16(v.x), h1 = __float2bfloat16(v.y);
    __nv_bfloat16 h2 = __float2bfloat16(v.z), h3 = __float2bfloat16(v.w);
    uint2 hu, lu;
    hu.x = (uint32_t)__bfloat16_as_ushort(h0) | ((uint32_t)__bfloat16_as_ushort(h1) << 16);
    hu.y = (uint32_t)__bfloat16_as_ushort(h2) | ((uint32_t)__bfloat16_as_ushort(h3) << 16);
    lu.x = packbf(v.x - __bfloat162float(h0), v.y - __bfloat162float(h1));
    lu.y = packbf(v.z - __bfloat162float(h2), v.w - __bfloat162float(h3));
    *reinterpret_cast<uint2*>(hp) = hu;
    *reinterpret_cast<uint2*>(lp) = lu;
}

__device__ __forceinline__ void store_pair(__nv_bfloat16* Ph, __nv_bfloat16* Pl,
                                           size_t off, float a, float b) {
    __nv_bfloat16 h0 = __float2bfloat16(a), h1 = __float2bfloat16(b);
    uint32_t hu = (uint32_t)__bfloat16_as_ushort(h0) | ((uint32_t)__bfloat16_as_ushort(h1) << 16);
    uint32_t lu = packbf(a - __bfloat162float(h0), b - __bfloat162float(h1));
    *reinterpret_cast<uint32_t*>(Ph + off) = hu;
    *reinterpret_cast<uint32_t*>(Pl + off) = lu;
}

// 2^y via FMA-pipe polynomial (no MUFU)
__device__ __forceinline__ float exp2p(float y) {
    y = fmaxf(y, -120.f);
    float t = y + 12582912.f;
    int   n = (__float_as_int(t) & 0x7FFFFF) - 0x400000;
    float f = y - (t - 12582912.f);
    float p = 1.3333558146e-3f;
    p = fmaf(p, f, 9.6181291076e-3f);
    p = fmaf(p, f, 5.5504108664e-2f);
    p = fmaf(p, f, 2.4022650695e-1f);
    p = fmaf(p, f, 6.9314718056e-1f);
    p = fmaf(p, f, 1.0f);
    return __int_as_float(__float_as_int(p) + (n << 23));
}

// ---------------------------------------------------------------------------
// Pre-split helpers
// ---------------------------------------------------------------------------
__global__ void split_plain(const float4* __restrict__ in,
                            __nv_bfloat16* __restrict__ h, __nv_bfloat16* __restrict__ l) {
    size_t i = (size_t)blockIdx.x * 256 + threadIdx.x;
    float4 v = in[i];
    split_store(h + 4 * i, l + 4 * i, v);
}

__global__ void trans_split(const float* __restrict__ in,
                            __nv_bfloat16* __restrict__ oh, __nv_bfloat16* __restrict__ ol) {
    __shared__ float t[32][33];
    int bx = blockIdx.x * 32, by = blockIdx.y * 32;
    #pragma unroll
    for (int i = 0; i < 32; i += 8)
        t[threadIdx.y + i][threadIdx.x] = in[(size_t)(by + threadIdx.y + i) * DMODEL + bx + threadIdx.x];
    __syncthreads();
    #pragma unroll
    for (int i = 0; i < 32; i += 8) {
        float v = t[threadIdx.x][threadIdx.y + i];
        size_t o = (size_t)(bx + threadIdx.y + i) * DMODEL + by + threadIdx.x;
        __nv_bfloat16 hv = __float2bfloat16(v);
        oh[o] = hv;
        ol[o] = __float2bfloat16(v - __bfloat162float(hv));
    }
}

// ---------------------------------------------------------------------------
// bf16x3 mma.sync GEMM: tile 256x128, BK=32, warp tile 64x64, 1 CTA/SM.
// 3-stage cp.async pipeline, XOR-swizzled 64B rows, 1 sync per chunk.
// Stage = Ah(16K)|Al(16K)|Bh(8K)|Bl(8K) = 48KB.
// ---------------------------------------------------------------------------
static constexpr int STAGE_B  = 49152;
static constexpr int SMEM_DYN = 3 * STAGE_B;     // 147456

template<int EPI>
__global__ __launch_bounds__(256, 1)
void gemm_bf16x3(const __nv_bfloat16* __restrict__ Ah, const __nv_bfloat16* __restrict__ Al,
                 const __nv_bfloat16* __restrict__ Bh, const __nv_bfloat16* __restrict__ Bl,
                 float* __restrict__ C,
                 const float* __restrict__ s0, const float* __restrict__ s1,
                 const float* __restrict__ s2,
                 __nv_bfloat16* __restrict__ P0h, __nv_bfloat16* __restrict__ P0l,
                 __nv_bfloat16* __restrict__ P1h, __nv_bfloat16* __restrict__ P1l,
                 __nv_bfloat16* __restrict__ P2h, __nv_bfloat16* __restrict__ P2l)
{
    extern __shared__ char smem[];
    const int tid  = threadIdx.x;
    const int lane = tid & 31;
    const int wid  = tid >> 5;
    const int bm   = blockIdx.y * 256;
    const int bn   = blockIdx.x * 128;
    const int wm0  = (wid & 3) * 64;     // warp m offset in tile
    const int wn0  = (wid >> 2) * 64;    // warp n offset in tile
    const uint32_t sbase = smem_u32(smem);

    // cp.async geometry: 64B rows, swizzled 16B chunk per thread
    const int crow = tid >> 2;            // 0..63
    const int cchk = (tid & 3) * 16;

    const char* gA_h = (const char*)Ah + (size_t)(bm + crow) * 2048 + cchk;
    const char* gA_l = (const char*)Al + (size_t)(bm + crow) * 2048 + cchk;
    const char* gB_h = (const char*)Bh + (size_t)(bn + crow) * 2048 + cchk;
    const char* gB_l = (const char*)Bl + (size_t)(bn + crow) * 2048 + cchk;

    uint32_t soA[4], soB[2];
    #pragma unroll
    for (int i = 0; i < 4; ++i)
        soA[i] = swz((uint32_t)((crow + 64 * i) * 64 + cchk));
    #pragma unroll
    for (int i = 0; i < 2; ++i)
        soB[i] = swz((uint32_t)((crow + 64 * i) * 64 + cchk));

    auto issue_stage = [&](int c, int s) {
        const size_t k0b = (size_t)c * 64;
        const uint32_t st = sbase + (uint32_t)s * STAGE_B;
        #pragma unroll
        for (int i = 0; i < 4; ++i) {
            CPASYNC16(st + soA[i],          gA_h + k0b + (size_t)(64 * i) * 2048);
            CPASYNC16(st + 16384u + soA[i], gA_l + k0b + (size_t)(64 * i) * 2048);
        }
        #pragma unroll
        for (int i = 0; i < 2; ++i) {
            CPASYNC16(st + 32768u + soB[i], gB_h + k0b + (size_t)(64 * i) * 2048);
            CPASYNC16(st + 40960u + soB[i], gB_l + k0b + (size_t)(64 * i) * 2048);
        }
        CPCOMMIT();
    };

    float acc[4][8][4];
    #pragma unroll
    for (int i = 0; i < 4; ++i)
        #pragma unroll
        for (int j = 0; j < 8; ++j)
            #pragma unroll
            for (int q = 0; q < 4; ++q) acc[i][j][q] = 0.f;

    uint32_t aoff[4], boff[4];
    #pragma unroll
    for (int mt = 0; mt < 4; ++mt)
        aoff[mt] = (uint32_t)((wm0 + mt * 16 + (lane & 15)) * 64 + ((lane >> 4) << 4));
    #pragma unroll
    for (int bb = 0; bb < 4; ++bb)
        boff[bb] = (uint32_t)((wn0 + bb * 16 + (lane & 7) + ((lane >> 4) << 3)) * 64 + ((lane & 8) << 1));

    auto compute = [&](int s) {
        const uint32_t st = sbase + (uint32_t)s * STAGE_B;
        #pragma unroll
        for (int ks = 0; ks < 2; ++ks) {
            const uint32_t kb = ks * 32u;
            uint32_t ah[4][4], al[4][4];
            #pragma unroll
            for (int mt = 0; mt < 4; ++mt) {
                const uint32_t off = swz(aoff[mt] + kb);
                LDMX4(ah[mt][0], ah[mt][1], ah[mt][2], ah[mt][3], st + off);
                LDMX4(al[mt][0], al[mt][1], al[mt][2], al[mt][3], st + 16384u + off);
            }
            #pragma unroll
            for (int bb = 0; bb < 4; ++bb) {
                const uint32_t off = swz(boff[bb] + kb);
                uint32_t b0, b1, b2, b3, e0, e1, e2, e3;
                LDMX4(b0, b1, b2, b3, st + 32768u + off);
                LDMX4(e0, e1, e2, e3, st + 40960u + off);
                #pragma unroll
                for (int mt = 0; mt < 4; ++mt) {
                    MMA16816_2(acc[mt][2 * bb],     ah[mt], b0, b1);
                    MMA16816_2(acc[mt][2 * bb],     ah[mt], e0, e1);
                    MMA16816_2(acc[mt][2 * bb],     al[mt], b0, b1);
                    MMA16816_2(acc[mt][2 * bb + 1], ah[mt], b2, b3);
                    MMA16816_2(acc[mt][2 * bb + 1], ah[mt], e2, e3);
                    MMA16816_2(acc[mt][2 * bb + 1], al[mt], b2, b3);
                }
            }
        }
    };

    issue_stage(0, 0);
    issue_stage(1, 1);

    for (int c = 0; c < 32; ++c) {
        if (c < 31) { CPWAIT(1); } else { CPWAIT(0); }
        __syncthreads();
        if (c + 2 < 32) issue_stage(c + 2, (c + 2) % 3);
        compute(c % 3);
    }

    // ---- epilogue
    #pragma unroll
    for (int mt = 0; mt < 4; ++mt) {
        const int m = bm + wm0 + mt * 16 + (lane >> 2);
        #pragma unroll
        for (int nf = 0; nf < 8; ++nf) {
            const int n = bn + wn0 + nf * 8 + (lane & 3) * 2;
            if (EPI == 0) {
                float2 v0 = {acc[mt][nf][0], acc[mt][nf][1]};
                float2 v1 = {acc[mt][nf][2], acc[mt][nf][3]};
                *reinterpret_cast<float2*>(C + (size_t)m * DMODEL + n) = v0;
                *reinterpret_cast<float2*>(C + (size_t)(m + 8) * DMODEL + n) = v1;
            } else {
                const size_t o0 = (size_t)m * DMODEL + n;
                const size_t o1 = (size_t)(m + 8) * DMODEL + n;
                float2 sc0 = *reinterpret_cast<const float2*>(s0 + n);
                store_pair(P0h, P0l, o0, acc[mt][nf][0] * sc0.x, acc[mt][nf][1] * sc0.y);
                store_pair(P0h, P0l, o1, acc[mt][nf][2] * sc0.x, acc[mt][nf][3] * sc0.y);
                if (EPI == 1) {
                    float2 sc1 = *reinterpret_cast<const float2*>(s1 + n);
                    float2 sc2 = *reinterpret_cast<const float2*>(s2 + n);
                    store_pair(P1h, P1l, o0, acc[mt][nf][0] * sc1.x, acc[mt][nf][1] * sc1.y);
                    store_pair(P1h, P1l, o1, acc[mt][nf][2] * sc1.x, acc[mt][nf][3] * sc1.y);
                    store_pair(P2h, P2l, o0, acc[mt][nf][0] * sc2.x, acc[mt][nf][1] * sc2.y);
                    store_pair(P2h, P2l, o1, acc[mt][nf][2] * sc2.x, acc[mt][nf][3] * sc2.y);
                }
            }
        }
    }
}

// ---------------------------------------------------------------------------
// mma.sync flash attention (unchanged)
// ---------------------------------------------------------------------------
static constexpr int RSA     = 72;
static constexpr int AT_MAT  = 64 * RSA;
static constexpr int AT_STG  = 4 * AT_MAT;
static constexpr int ASMEM   = 2 * AT_STG * 2;

__global__ __launch_bounds__(256, 1)
void attn_mma(const float* __restrict__ Q, const float* __restrict__ K,
              const float* __restrict__ V, const float* __restrict__ bias,
              __nv_bfloat16* __restrict__ AOh, __nv_bfloat16* __restrict__ AOl)
{
    extern __shared__ __nv_bfloat16 asmem[];
    const int tid  = threadIdx.x;
    const int lane = tid & 31;
    const int w    = tid >> 5;
    const int qt   = (int)gridDim.x - 1 - (int)blockIdx.x;
    const int h    = blockIdx.y;
    const int b    = blockIdx.z;
    const int q0   = qt * 128;
    const uint32_t sbase = smem_u32(asmem);

    {
        const float* Qb = Q + ((size_t)(b * SEQ + q0)) * DMODEL + h * DHEAD;
        #pragma unroll
        for (int i = 0; i < 8; ++i) {
            int idx = tid + i * 256;
            int row = idx >> 4, c4 = (idx & 15) * 4;
            float4 v = *reinterpret_cast<const float4*>(Qb + (size_t)row * DMODEL + c4);
            int off = row * RSA + c4;
            split_store(asmem + AT_STG + off, asmem + AT_STG + 128 * RSA + off, v);
        }
    }
    __syncthreads();
    uint32_t qh[4][4], ql[4][4];
    #pragma unroll
    for (int ks = 0; ks < 4; ++ks) {
        const uint32_t off = ((w * 16 + (lane & 15)) * RSA + ks * 16 + ((lane >> 4) << 3)) * 2;
        LDMX4(qh[ks][0], qh[ks][1], qh[ks][2], qh[ks][3], sbase + AT_STG * 2 + off);
        LDMX4(ql[ks][0], ql[ks][1], ql[ks][2], ql[ks][3], sbase + (AT_STG + 128 * RSA) * 2 + off);
    }
    __syncthreads();

    float m0 = -1e30f, m1 = -1e30f, l0 = 0.f, l1 = 0.f;
    float o[8][4];
    #pragma unroll
    for (int j = 0; j < 8; ++j)
        #pragma unroll
        for (int q = 0; q < 4; ++q) o[j][q] = 0.f;

    const int q_r0 = q0 + w * 16 + (lane >> 2);
    const int q_r1 = q_r0 + 8;
    const float* bph = bias + (size_t)h * SEQ * SEQ;
    const int nt = 2 * qt + 2;

    const int grow = tid >> 4;
    const int gc4  = (tid & 15) * 4;
    float4 kreg[4], vreg[4];

    auto load_tile = [&](int kt) {
        const int k0 = kt * 64;
        const float* Kb = K + ((size_t)(b * SEQ + k0 + grow)) * DMODEL + h * DHEAD + gc4;
        const float* Vb = V + ((size_t)(b * SEQ + k0 + grow)) * DMODEL + h * DHEAD + gc4;
        #pragma unroll
        for (int i = 0; i < 4; ++i) kreg[i] = *reinterpret_cast<const float4*>(Kb + (size_t)i * 16 * DMODEL);
        #pragma unroll
        for (int i = 0; i < 4; ++i) vreg[i] = *reinterpret_cast<const float4*>(Vb + (size_t)i * 16 * DMODEL);
    };
    auto store_tile = [&](int s) {
        __nv_bfloat16* st = asmem + s * AT_STG;
        #pragma unroll
        for (int i = 0; i < 4; ++i) {
            const int off = (grow + i * 16) * RSA + gc4;
            split_store(st + off,              st + AT_MAT + off,     kreg[i]);
            split_store(st + 2 * AT_MAT + off, st + 3 * AT_MAT + off, vreg[i]);
        }
    };

    load_tile(0);
    store_tile(0);
    __syncthreads();

    for (int kt = 0; kt < nt; ++kt) {
        const int s  = kt & 1;
        const int k0 = kt * 64;
        if (kt + 1 < nt) load_tile(kt + 1);

        const uint32_t Khu = sbase + s * AT_STG * 2;
        const uint32_t Klu = Khu + AT_MAT * 2;
        const uint32_t Vhu = Khu + 2 * AT_MAT * 2;
        const uint32_t Vlu = Khu + 3 * AT_MAT * 2;

        float sacc[8][4];
        #pragma unroll
        for (int j = 0; j < 8; ++j)
            #pragma unroll
            for (int q = 0; q < 4; ++q) sacc[j][q] = 0.f;
        #pragma unroll
        for (int ks = 0; ks < 4; ++ks) {
            #pragma unroll
            for (int bb = 0; bb < 4; ++bb) {
                const uint32_t off =
                    ((bb * 16 + (lane & 7) + ((lane >> 4) << 3)) * RSA + ks * 16 + (lane & 8)) * 2;
                uint32_t h0, h1, h2, h3, e0, e1, e2, e3;
                LDMX4(h0, h1, h2, h3, Khu + off);
                LDMX4(e0, e1, e2, e3, Klu + off);
                MMA16816_2(sacc[2 * bb],     qh[ks], h0, h1);
                MMA16816_2(sacc[2 * bb],     qh[ks], e0, e1);
                MMA16816_2(sacc[2 * bb],     ql[ks], h0, h1);
                MMA16816_2(sacc[2 * bb + 1], qh[ks], h2, h3);
                MMA16816_2(sacc[2 * bb + 1], qh[ks], e2, e3);
                MMA16816_2(sacc[2 * bb + 1], ql[ks], h2, h3);
            }
        }

        const bool mask = (kt >= 2 * qt);
        const float* r0p = bph + (size_t)q_r0 * SEQ + k0 + 2 * (lane & 3);
        const float* r1p = bph + (size_t)q_r1 * SEQ + k0 + 2 * (lane & 3);
        #pragma unroll
        for (int nf = 0; nf < 8; ++nf) {
            float2 b0 = *reinterpret_cast<const float2*>(r0p + nf * 8);
            float2 b1 = *reinterpret_cast<const float2*>(r1p + nf * 8);
            float v0 = fmaf(sacc[nf][0], 0.18033688f, b0.x * 1.4426950f);
            float v1 = fmaf(sacc[nf][1], 0.18033688f, b0.y * 1.4426950f);
            float v2 = fmaf(sacc[nf][2], 0.18033688f, b1.x * 1.4426950f);
            float v3 = fmaf(sacc[nf][3], 0.18033688f, b1.y * 1.4426950f);
            if (mask) {
                const int kc = k0 + nf * 8 + 2 * (lane & 3);
                if (kc     > q_r0) v0 = -1e30f;
                if (kc + 1 > q_r0) v1 = -1e30f;
                if (kc     > q_r1) v2 = -1e30f;
                if (kc + 1 > q_r1) v3 = -1e30f;
            }
            sacc[nf][0] = v0; sacc[nf][1] = v1; sacc[nf][2] = v2; sacc[nf][3] = v3;
        }

        float m0n = m0, m1n = m1;
        #pragma unroll
        for (int nf = 0; nf < 8; ++nf) {
            m0n = fmaxf(m0n, fmaxf(sacc[nf][0], sacc[nf][1]));
            m1n = fmaxf(m1n, fmaxf(sacc[nf][2], sacc[nf][3]));
        }
        m0n = fmaxf(m0n, __shfl_xor_sync(0xffffffffu, m0n, 1));
        m0n = fmaxf(m0n, __shfl_xor_sync(0xffffffffu, m0n, 2));
        m1n = fmaxf(m1n, __shfl_xor_sync(0xffffffffu, m1n, 1));
        m1n = fmaxf(m1n, __shfl_xor_sync(0xffffffffu, m1n, 2));
        const float c0 = exp2p(m0 - m0n), c1 = exp2p(m1 - m1n);
        m0 = m0n; m1 = m1n;
        l0 *= c0;  l1 *= c1;
        #pragma unroll
        for (int nf = 0; nf < 8; ++nf) {
            o[nf][0] *= c0; o[nf][1] *= c0;
            o[nf][2] *= c1; o[nf][3] *= c1;
        }

        uint32_t pA0[8], pA1[8], pL0[8], pL1[8];
        #pragma unroll
        for (int nf = 0; nf < 8; ++nf) {
            float p0 = exp2p(sacc[nf][0] - m0);
            float p1 = exp2p(sacc[nf][1] - m0);
            float p2 = exp2p(sacc[nf][2] - m1);
            float p3 = exp2p(sacc[nf][3] - m1);
            l0 += p0 + p1; l1 += p2 + p3;
            __nv_bfloat16 h0 = __float2bfloat16(p0), h1 = __float2bfloat16(p1);
            __nv_bfloat16 h2 = __float2bfloat16(p2), h3 = __float2bfloat16(p3);
            pA0[nf] = (uint32_t)__bfloat16_as_ushort(h0) | ((uint32_t)__bfloat16_as_ushort(h1) << 16);
            pA1[nf] = (uint32_t)__bfloat16_as_ushort(h2) | ((uint32_t)__bfloat16_as_ushort(h3) << 16);
            pL0[nf] = packbf(p0 - __bfloat162float(h0), p1 - __bfloat162float(h1));
            pL1[nf] = packbf(p2 - __bfloat162float(h2), p3 - __bfloat162float(h3));
        }

        #pragma unroll
        for (int ks = 0; ks < 4; ++ks) {
            uint32_t ah[4] = { pA0[2 * ks], pA1[2 * ks], pA0[2 * ks + 1], pA1[2 * ks + 1] };
            uint32_t al[4] = { pL0[2 * ks], pL1[2 * ks], pL0[2 * ks + 1], pL1[2 * ks + 1] };
            #pragma unroll
            for (int ng = 0; ng < 4; ++ng) {
                const uint32_t off =
                    ((ks * 16 + (lane & 7) + (lane & 8)) * RSA + ng * 16 + ((lane >> 4) << 3)) * 2;
                uint32_t h0, h1, h2, h3, e0, e1, e2, e3;
                LDMX4T(h0, h1, h2, h3, Vhu + off);
                LDMX4T(e0, e1, e2, e3, Vlu + off);
                MMA16816_2(o[2 * ng],     ah, h0, h1);
                MMA16816_2(o[2 * ng],     al, h0, h1);
                MMA16816_2(o[2 * ng],     ah, e0, e1);
                MMA16816_2(o[2 * ng + 1], ah, h2, h3);
                MMA16816_2(o[2 * ng + 1], al, h2, h3);
                MMA16816_2(o[2 * ng + 1], ah, e2, e3);
            }
        }

        if (kt + 1 < nt) store_tile((kt + 1) & 1);
        __syncthreads();
    }

    l0 += __shfl_xor_sync(0xffffffffu, l0, 1);
    l0 += __shfl_xor_sync(0xffffffffu, l0, 2);
    l1 += __shfl_xor_sync(0xffffffffu, l1, 1);
    l1 += __shfl_xor_sync(0xffffffffu, l1, 2);
    const float i0 = 1.f / l0, i1 = 1.f / l1;
    const size_t r0off = (size_t)(b * SEQ + q_r0) * DMODEL + h * DHEAD + 2 * (lane & 3);
    const size_t r1off = (size_t)(b * SEQ + q_r1) * DMODEL + h * DHEAD + 2 * (lane & 3);
    #pragma unroll
    for (int nf = 0; nf < 8; ++nf) {
        store_pair(AOh, AOl, r0off + nf * 8, o[nf][0] * i0, o[nf][1] * i0);
        store_pair(AOh, AOl, r1off + nf * 8, o[nf][2] * i1, o[nf][3] * i1);
    }
}

// ---------------------------------------------------------------------------
extern "C" void kernel_launch(void* const* d_in, const int* in_sizes, int n_in,
                              void* d_out, int out_size)
{
    const float* x     = (const float*)d_in[0];
    const float* basis = (const float*)d_in[1];
    const float* sq    = (const float*)d_in[2];
    const float* sk    = (const float*)d_in[3];
    const float* sv    = (const float*)d_in[4];
    const float* so    = (const float*)d_in[5];
    const float* bias  = (const float*)d_in[6];
    float*       out   = (float*)d_out;

    __nv_bfloat16 *Xh, *Xl, *BTh, *BTl, *Bmh, *Bml;
    __nv_bfloat16 *XBqh, *XBql, *XBkh, *XBkl, *XBvh, *XBvl;
    __nv_bfloat16 *AOh, *AOl, *O1h, *O1l;
    float *Qm, *Km, *Vm;
    cudaGetSymbolAddress((void**)&Xh,  g_Xh);  cudaGetSymbolAddress((void**)&Xl,  g_Xl);
    cudaGetSymbolAddress((void**)&BTh, g_BTh); cudaGetSymbolAddress((void**)&BTl, g_BTl);
    cudaGetSymbolAddress((void**)&Bmh, g_Bmh); cudaGetSymbolAddress((void**)&Bml, g_Bml);
    cudaGetSymbolAddress((void**)&XBqh, g_XBqh); cudaGetSymbolAddress((void**)&XBql, g_XBql);
    cudaGetSymbolAddress((void**)&XBkh, g_XBkh); cudaGetSymbolAddress((void**)&XBkl, g_XBkl);
    cudaGetSymbolAddress((void**)&XBvh, g_XBvh); cudaGetSymbolAddress((void**)&XBvl, g_XBvl);
    cudaGetSymbolAddress((void**)&AOh, g_AOh); cudaGetSymbolAddress((void**)&AOl, g_AOl);
    cudaGetSymbolAddress((void**)&O1h, g_O1h); cudaGetSymbolAddress((void**)&O1l, g_O1l);
    cudaGetSymbolAddress((void**)&Qm, g_Q);
    cudaGetSymbolAddress((void**)&Km, g_K);
    cudaGetSymbolAddress((void**)&Vm, g_V);

    cudaFuncSetAttribute(gemm_bf16x3<0>, cudaFuncAttributeMaxDynamicSharedMemorySize, SMEM_DYN);
    cudaFuncSetAttribute(gemm_bf16x3<1>, cudaFuncAttributeMaxDynamicSharedMemorySize, SMEM_DYN);
    cudaFuncSetAttribute(gemm_bf16x3<2>, cudaFuncAttributeMaxDynamicSharedMemorySize, SMEM_DYN);
    cudaFuncSetAttribute(attn_mma, cudaFuncAttributeMaxDynamicSharedMemorySize, ASMEM);

    // pre-split inputs
    split_plain<<<MROWS * DMODEL / 1024, 256>>>((const float4*)x, Xh, Xl);
    split_plain<<<DMODEL * DMODEL / 1024, 256>>>((const float4*)basis, Bmh, Bml);
    trans_split<<<dim3(32, 32), dim3(32, 8)>>>(basis, BTh, BTl);

    const dim3 gg(DMODEL / 128, MROWS / 256);     // (8, 16) = 128 CTAs, 1 wave
    // G1: XB = X @ basis, epilogue emits scale-fused pairs for q/k/v
    gemm_bf16x3<1><<<gg, 256, SMEM_DYN>>>(Xh, Xl, BTh, BTl, nullptr,
                                          sq, sk, sv,
                                          XBqh, XBql, XBkh, XBkl, XBvh, XBvl);
    // G2-4: Q/K/V fp32
    gemm_bf16x3<0><<<gg, 256, SMEM_DYN>>>(XBqh, XBql, Bmh, Bml, Qm,
                                          nullptr, nullptr, nullptr,
                                          nullptr, nullptr, nullptr, nullptr, nullptr, nullptr);
    gemm_bf16x3<0><<<gg, 256, SMEM_DYN>>>(XBkh, XBkl, Bmh, Bml, Km,
                                          nullptr, nullptr, nullptr,
                                          nullptr, nullptr, nullptr, nullptr, nullptr, nullptr);
    gemm_bf16x3<0><<<gg, 256, SMEM_DYN>>>(XBvh, XBvl, Bmh, Bml, Vm,
                                          nullptr, nullptr, nullptr,
                                          nullptr, nullptr, nullptr, nullptr, nullptr, nullptr);

    attn_mma<<<dim3(SEQ / 128, NHEADS, BATCH), 256, ASMEM>>>(Qm, Km, Vm, bias, AOh, AOl);

    // G5: O1 = AO @ basis, epilogue emits so-fused pair
    gemm_bf16x3<2><<<gg, 256, SMEM_DYN>>>(AOh, AOl, BTh, BTl, nullptr,
                                          so, nullptr, nullptr,
                                          O1h, O1l, nullptr, nullptr, nullptr, nullptr);
    // G6: out = O1s @ basis^T, fp32
    gemm_bf16x3<0><<<gg, 256, SMEM_DYN>>>(O1h, O1l, Bmh, Bml, out,
                                          nullptr, nullptr, nullptr,
                                          nullptr, nullptr, nullptr, nullptr, nullptr, nullptr);
}

// round 8
// speedup vs baseline: 1.3495x; 1.3495x over previous
#include <cuda_runtime.h>
#include <cuda_fp16.h>
#include <cstdint>
#include <cstddef>

#define SEQ    2048
#define BATCH  2
#define DMODEL 1024
#define NHEADS 16
#define DHEAD  64
#define MROWS  (BATCH*SEQ)

// ---------------- scratch (device globals; allocation-free rule) ------------
__device__ __half g_Xh [(size_t)MROWS*DMODEL], g_Xl [(size_t)MROWS*DMODEL];
__device__ __half g_BTh[(size_t)DMODEL*DMODEL];            // basis^T, fp16
__device__ __half g_Bmh[(size_t)DMODEL*DMODEL];            // basis, fp16
__device__ __half g_XBqh[(size_t)MROWS*DMODEL], g_XBql[(size_t)MROWS*DMODEL];
__device__ __half g_XBkh[(size_t)MROWS*DMODEL], g_XBkl[(size_t)MROWS*DMODEL];
__device__ __half g_XBvh[(size_t)MROWS*DMODEL], g_XBvl[(size_t)MROWS*DMODEL];
__device__ __half g_AOh[(size_t)MROWS*DMODEL],  g_AOl[(size_t)MROWS*DMODEL];
__device__ __half g_O1h[(size_t)MROWS*DMODEL],  g_O1l[(size_t)MROWS*DMODEL];
__device__ float g_Q[(size_t)MROWS*DMODEL], g_K[(size_t)MROWS*DMODEL], g_V[(size_t)MROWS*DMODEL];

// ---------------------------------------------------------------------------
__device__ __forceinline__ uint32_t smem_u32(const void* p) {
    uint32_t a;
    asm("{ .reg .u64 t; cvta.to.shared.u64 t, %1; cvt.u32.u64 %0, t; }"
        : "=r"(a) : "l"(p));
    return a;
}

#define LDMX4(r0, r1, r2, r3, addr) \
    asm volatile("ldmatrix.sync.aligned.m8n8.x4.shared.b16 {%0,%1,%2,%3}, [%4];" \
                 : "=r"(r0), "=r"(r1), "=r"(r2), "=r"(r3) : "r"(addr))

#define LDMX4T(r0, r1, r2, r3, addr) \
    asm volatile("ldmatrix.sync.aligned.m8n8.x4.trans.shared.b16 {%0,%1,%2,%3}, [%4];" \
                 : "=r"(r0), "=r"(r1), "=r"(r2), "=r"(r3) : "r"(addr))

#define MMA16816_2(d, a, b0r, b1r) \
    asm volatile("mma.sync.aligned.m16n8k16.row.col.f32.f16.f16.f32 " \
                 "{%0,%1,%2,%3}, {%4,%5,%6,%7}, {%8,%9}, {%0,%1,%2,%3};" \
                 : "+f"((d)[0]), "+f"((d)[1]), "+f"((d)[2]), "+f"((d)[3]) \
                 : "r"((a)[0]), "r"((a)[1]), "r"((a)[2]), "r"((a)[3]), \
                   "r"(b0r), "r"(b1r))

#define CPASYNC16(dst, src) \
    asm volatile("cp.async.cg.shared.global [%0], [%1], 16;" \
                 :: "r"(dst), "l"(src))
#define CPCOMMIT()  asm volatile("cp.async.commit_group;" ::: "memory")
#define CPWAIT(n)   asm volatile("cp.async.wait_group %0;" :: "n"(n) : "memory")

// XOR swizzle: 16B chunk index ^= row-pair (64B rows, conflict-free ldmatrix)
__device__ __forceinline__ uint32_t swz(uint32_t o) {
    return o ^ (((o >> 7) & 3u) << 4);
}

__device__ __forceinline__ uint32_t packh(float a, float b) {
    __half x = __float2half(a), y = __float2half(b);
    return (uint32_t)__half_as_ushort(x) | ((uint32_t)__half_as_ushort(y) << 16);
}

// fp32x4 -> fp16 hi/lo split, two 8-byte stores
__device__ __forceinline__ void split_store(void* hp, void* lp, float4 v) {
    __half h0 = __float2half(v.x), h1 = __float2half(v.y);
    __half h2 = __float2half(v.z), h3 = __float2half(v.w);
    uint2 hu, lu;
    hu.x = (uint32_t)__half_as_ushort(h0) | ((uint32_t)__half_as_ushort(h1) << 16);
    hu.y = (uint32_t)__half_as_ushort(h2) | ((uint32_t)__half_as_ushort(h3) << 16);
    lu.x = packh(v.x - __half2float(h0), v.y - __half2float(h1));
    lu.y = packh(v.z - __half2float(h2), v.w - __half2float(h3));
    *reinterpret_cast<uint2*>(hp) = hu;
    *reinterpret_cast<uint2*>(lp) = lu;
}

// fp32x4 -> fp16 single, one 8-byte store
__device__ __forceinline__ void trunc_store(void* hp, float4 v) {
    uint2 hu;
    hu.x = packh(v.x, v.y);
    hu.y = packh(v.z, v.w);
    *reinterpret_cast<uint2*>(hp) = hu;
}

__device__ __forceinline__ void store_pair(__half* Ph, __half* Pl,
                                           size_t off, float a, float b) {
    __half h0 = __float2half(a), h1 = __float2half(b);
    uint32_t hu = (uint32_t)__half_as_ushort(h0) | ((uint32_t)__half_as_ushort(h1) << 16);
    uint32_t lu = packh(a - __half2float(h0), b - __half2float(h1));
    *reinterpret_cast<uint32_t*>(Ph + off) = hu;
    *reinterpret_cast<uint32_t*>(Pl + off) = lu;
}

// 2^y via FMA-pipe polynomial (no MUFU)
__device__ __forceinline__ float exp2p(float y) {
    y = fmaxf(y, -120.f);
    float t = y + 12582912.f;
    int   n = (__float_as_int(t) & 0x7FFFFF) - 0x400000;
    float f = y - (t - 12582912.f);
    float p = 1.3333558146e-3f;
    p = fmaf(p, f, 9.6181291076e-3f);
    p = fmaf(p, f, 5.5504108664e-2f);
    p = fmaf(p, f, 2.4022650695e-1f);
    p = fmaf(p, f, 6.9314718056e-1f);
    p = fmaf(p, f, 1.0f);
    return __int_as_float(__float_as_int(p) + (n << 23));
}

// ---------------------------------------------------------------------------
// Pre-split helpers
// ---------------------------------------------------------------------------
__global__ void split_plain(const float4* __restrict__ in,
                            __half* __restrict__ h, __half* __restrict__ l) {
    size_t i = (size_t)blockIdx.x * 256 + threadIdx.x;
    float4 v = in[i];
    split_store(h + 4 * i, l + 4 * i, v);
}

__global__ void trunc_plain(const float4* __restrict__ in, __half* __restrict__ h) {
    size_t i = (size_t)blockIdx.x * 256 + threadIdx.x;
    trunc_store(h + 4 * i, in[i]);
}

__global__ void trans_trunc(const float* __restrict__ in, __half* __restrict__ oh) {
    __shared__ float t[32][33];
    int bx = blockIdx.x * 32, by = blockIdx.y * 32;
    #pragma unroll
    for (int i = 0; i < 32; i += 8)
        t[threadIdx.y + i][threadIdx.x] = in[(size_t)(by + threadIdx.y + i) * DMODEL + bx + threadIdx.x];
    __syncthreads();
    #pragma unroll
    for (int i = 0; i < 32; i += 8) {
        float v = t[threadIdx.x][threadIdx.y + i];
        oh[(size_t)(bx + threadIdx.y + i) * DMODEL + by + threadIdx.x] = __float2half(v);
    }
}

// ---------------------------------------------------------------------------
// fp16x2 mma.sync GEMM: C[m,n] = sum_k A[m,k]*B[n,k], A=(Ah+Al) fp16, B fp16.
// Tile 128x128, BK=32, warp tile 32x64, 4-stage cp.async, XOR-swizzled 64B rows.
// Stage = Ah(8K)|Al(8K)|Bh(8K) = 24KB; 4 stages = 96KB; 2 CTAs/SM.
// ---------------------------------------------------------------------------
static constexpr int STAGE_B  = 24576;
static constexpr int SMEM_DYN = 4 * STAGE_B;     // 98304

template<int EPI>
__global__ __launch_bounds__(256, 2)
void gemm_fp16x2(const __half* __restrict__ Ah, const __half* __restrict__ Al,
                 const __half* __restrict__ Bh,
                 float* __restrict__ C,
                 const float* __restrict__ s0, const float* __restrict__ s1,
                 const float* __restrict__ s2,
                 __half* __restrict__ P0h, __half* __restrict__ P0l,
                 __half* __restrict__ P1h, __half* __restrict__ P1l,
                 __half* __restrict__ P2h, __half* __restrict__ P2l)
{
    extern __shared__ char smem[];
    const int tid  = threadIdx.x;
    const int lane = tid & 31;
    const int wid  = tid >> 5;
    const int bm   = blockIdx.y * 128;
    const int bn   = blockIdx.x * 128;
    const int wm0  = (wid & 3) * 32;
    const int wn0  = (wid >> 2) * 64;
    const uint32_t sbase = smem_u32(smem);

    const int crow = tid >> 2;            // 0..63
    const int cchk = (tid & 3) * 16;

    const char* gA_h = (const char*)Ah + (size_t)(bm + crow) * 2048 + cchk;
    const char* gA_l = (const char*)Al + (size_t)(bm + crow) * 2048 + cchk;
    const char* gB_h = (const char*)Bh + (size_t)(bn + crow) * 2048 + cchk;

    const uint32_t so1 = swz((uint32_t)(crow * 64 + cchk));
    const uint32_t so2 = swz((uint32_t)(crow * 64 + cchk) + 4096u);

    auto issue_stage = [&](int c, int s) {
        const size_t k0b = (size_t)c * 64;
        const uint32_t st = sbase + (uint32_t)s * STAGE_B;
        CPASYNC16(st + so1,          gA_h + k0b);
        CPASYNC16(st + so2,          gA_h + k0b + (size_t)64 * 2048);
        CPASYNC16(st + 8192u  + so1, gA_l + k0b);
        CPASYNC16(st + 8192u  + so2, gA_l + k0b + (size_t)64 * 2048);
        CPASYNC16(st + 16384u + so1, gB_h + k0b);
        CPASYNC16(st + 16384u + so2, gB_h + k0b + (size_t)64 * 2048);
        CPCOMMIT();
    };

    float acc[2][8][4];
    #pragma unroll
    for (int i = 0; i < 2; ++i)
        #pragma unroll
        for (int j = 0; j < 8; ++j)
            #pragma unroll
            for (int q = 0; q < 4; ++q) acc[i][j][q] = 0.f;

    uint32_t aoff[2], boff[4];
    #pragma unroll
    for (int mt = 0; mt < 2; ++mt)
        aoff[mt] = (uint32_t)((wm0 + mt * 16 + (lane & 15)) * 64 + ((lane >> 4) << 4));
    #pragma unroll
    for (int bb = 0; bb < 4; ++bb)
        boff[bb] = (uint32_t)((wn0 + bb * 16 + (lane & 7) + ((lane >> 4) << 3)) * 64 + ((lane & 8) << 1));

    auto compute = [&](int s) {
        const uint32_t st = sbase + (uint32_t)s * STAGE_B;
        #pragma unroll
        for (int ks = 0; ks < 2; ++ks) {
            const uint32_t kb = ks * 32u;
            uint32_t ah[2][4], al[2][4];
            #pragma unroll
            for (int mt = 0; mt < 2; ++mt) {
                const uint32_t off = swz(aoff[mt] + kb);
                LDMX4(ah[mt][0], ah[mt][1], ah[mt][2], ah[mt][3], st + off);
                LDMX4(al[mt][0], al[mt][1], al[mt][2], al[mt][3], st + 8192u + off);
            }
            #pragma unroll
            for (int bb = 0; bb < 4; ++bb) {
                const uint32_t off = swz(boff[bb] + kb);
                uint32_t b0, b1, b2, b3;
                LDMX4(b0, b1, b2, b3, st + 16384u + off);
                #pragma unroll
                for (int mt = 0; mt < 2; ++mt) {
                    MMA16816_2(acc[mt][2 * bb],     ah[mt], b0, b1);
                    MMA16816_2(acc[mt][2 * bb],     al[mt], b0, b1);
                    MMA16816_2(acc[mt][2 * bb + 1], ah[mt], b2, b3);
                    MMA16816_2(acc[mt][2 * bb + 1], al[mt], b2, b3);
                }
            }
        }
    };

    issue_stage(0, 0);
    issue_stage(1, 1);
    issue_stage(2, 2);

    for (int c = 0; c < 32; ++c) {
        if (c <= 29)      { CPWAIT(2); }
        else if (c == 30) { CPWAIT(1); }
        else              { CPWAIT(0); }
        __syncthreads();
        if (c + 3 < 32) issue_stage(c + 3, (c + 3) & 3);
        compute(c & 3);
    }

    // ---- epilogue
    #pragma unroll
    for (int mt = 0; mt < 2; ++mt) {
        const int m = bm + wm0 + mt * 16 + (lane >> 2);
        #pragma unroll
        for (int nf = 0; nf < 8; ++nf) {
            const int n = bn + wn0 + nf * 8 + (lane & 3) * 2;
            if (EPI == 0) {
                float2 v0 = {acc[mt][nf][0], acc[mt][nf][1]};
                float2 v1 = {acc[mt][nf][2], acc[mt][nf][3]};
                *reinterpret_cast<float2*>(C + (size_t)m * DMODEL + n) = v0;
                *reinterpret_cast<float2*>(C + (size_t)(m + 8) * DMODEL + n) = v1;
            } else {
                const size_t o0 = (size_t)m * DMODEL + n;
                const size_t o1 = (size_t)(m + 8) * DMODEL + n;
                float2 sc0 = *reinterpret_cast<const float2*>(s0 + n);
                store_pair(P0h, P0l, o0, acc[mt][nf][0] * sc0.x, acc[mt][nf][1] * sc0.y);
                store_pair(P0h, P0l, o1, acc[mt][nf][2] * sc0.x, acc[mt][nf][3] * sc0.y);
                if (EPI == 1) {
                    float2 sc1 = *reinterpret_cast<const float2*>(s1 + n);
                    float2 sc2 = *reinterpret_cast<const float2*>(s2 + n);
                    store_pair(P1h, P1l, o0, acc[mt][nf][0] * sc1.x, acc[mt][nf][1] * sc1.y);
                    store_pair(P1h, P1l, o1, acc[mt][nf][2] * sc1.x, acc[mt][nf][3] * sc1.y);
                    store_pair(P2h, P2l, o0, acc[mt][nf][0] * sc2.x, acc[mt][nf][1] * sc2.y);
                    store_pair(P2h, P2l, o1, acc[mt][nf][2] * sc2.x, acc[mt][nf][3] * sc2.y);
                }
            }
        }
    }
}

// ---------------------------------------------------------------------------
// fp16x2 mma.sync flash attention: Q split / K single, P split / V single.
// ---------------------------------------------------------------------------
static constexpr int RSA     = 72;                 // fp16 elems per row (64+8 pad)
static constexpr int AT_MAT  = 64 * RSA;           // one 64x64 tile (elems)
static constexpr int AT_STG  = 2 * AT_MAT;         // Kh, Vh
static constexpr int ASMEM   = 2 * AT_STG * 2;     // bytes = 36864

__global__ __launch_bounds__(256, 1)
void attn_mma(const float* __restrict__ Q, const float* __restrict__ K,
              const float* __restrict__ V, const float* __restrict__ bias,
              __half* __restrict__ AOh, __half* __restrict__ AOl)
{
    extern __shared__ __half asmem[];
    const int tid  = threadIdx.x;
    const int lane = tid & 31;
    const int w    = tid >> 5;
    const int qt   = (int)gridDim.x - 1 - (int)blockIdx.x;
    const int h    = blockIdx.y;
    const int b    = blockIdx.z;
    const int q0   = qt * 128;
    const uint32_t sbase = smem_u32(asmem);

    // ---- stage Q (128x64) split hi/lo into smem (overlaps K/V stages; freed after)
    {
        const float* Qb = Q + ((size_t)(b * SEQ + q0)) * DMODEL + h * DHEAD;
        #pragma unroll
        for (int i = 0; i < 8; ++i) {
            int idx = tid + i * 256;
            int row = idx >> 4, c4 = (idx & 15) * 4;
            float4 v = *reinterpret_cast<const float4*>(Qb + (size_t)row * DMODEL + c4);
            int off = row * RSA + c4;
            split_store(asmem + off, asmem + 128 * RSA + off, v);
        }
    }
    __syncthreads();
    uint32_t qh[4][4], ql[4][4];
    #pragma unroll
    for (int ks = 0; ks < 4; ++ks) {
        const uint32_t off = ((w * 16 + (lane & 15)) * RSA + ks * 16 + ((lane >> 4) << 3)) * 2;
        LDMX4(qh[ks][0], qh[ks][1], qh[ks][2], qh[ks][3], sbase + off);
        LDMX4(ql[ks][0], ql[ks][1], ql[ks][2], ql[ks][3], sbase + 128 * RSA * 2 + off);
    }
    __syncthreads();

    float m0 = -1e30f, m1 = -1e30f, l0 = 0.f, l1 = 0.f;
    float o[8][4];
    #pragma unroll
    for (int j = 0; j < 8; ++j)
        #pragma unroll
        for (int q = 0; q < 4; ++q) o[j][q] = 0.f;

    const int q_r0 = q0 + w * 16 + (lane >> 2);
    const int q_r1 = q_r0 + 8;
    const float* bph = bias + (size_t)h * SEQ * SEQ;
    const int nt = 2 * qt + 2;

    const int grow = tid >> 4;
    const int gc4  = (tid & 15) * 4;
    float4 kreg[4], vreg[4];

    auto load_tile = [&](int kt) {
        const int k0 = kt * 64;
        const float* Kb = K + ((size_t)(b * SEQ + k0 + grow)) * DMODEL + h * DHEAD + gc4;
        const float* Vb = V + ((size_t)(b * SEQ + k0 + grow)) * DMODEL + h * DHEAD + gc4;
        #pragma unroll
        for (int i = 0; i < 4; ++i) kreg[i] = *reinterpret_cast<const float4*>(Kb + (size_t)i * 16 * DMODEL);
        #pragma unroll
        for (int i = 0; i < 4; ++i) vreg[i] = *reinterpret_cast<const float4*>(Vb + (size_t)i * 16 * DMODEL);
    };
    auto store_tile = [&](int s) {
        __half* st = asmem + s * AT_STG;
        #pragma unroll
        for (int i = 0; i < 4; ++i) {
            const int off = (grow + i * 16) * RSA + gc4;
            trunc_store(st + off,          kreg[i]);
            trunc_store(st + AT_MAT + off, vreg[i]);
        }
    };

    load_tile(0);
    store_tile(0);
    __syncthreads();

    for (int kt = 0; kt < nt; ++kt) {
        const int s  = kt & 1;
        const int k0 = kt * 64;
        if (kt + 1 < nt) load_tile(kt + 1);

        const uint32_t Khu = sbase + s * AT_STG * 2;
        const uint32_t Vhu = Khu + AT_MAT * 2;

        // ---- S = Q K^T  (Q split, K single)
        float sacc[8][4];
        #pragma unroll
        for (int j = 0; j < 8; ++j)
            #pragma unroll
            for (int q = 0; q < 4; ++q) sacc[j][q] = 0.f;
        #pragma unroll
        for (int ks = 0; ks < 4; ++ks) {
            #pragma unroll
            for (int bb = 0; bb < 4; ++bb) {
                const uint32_t off =
                    ((bb * 16 + (lane & 7) + ((lane >> 4) << 3)) * RSA + ks * 16 + (lane & 8)) * 2;
                uint32_t b0, b1, b2, b3;
                LDMX4(b0, b1, b2, b3, Khu + off);
                MMA16816_2(sacc[2 * bb],     qh[ks], b0, b1);
                MMA16816_2(sacc[2 * bb],     ql[ks], b0, b1);
                MMA16816_2(sacc[2 * bb + 1], qh[ks], b2, b3);
                MMA16816_2(sacc[2 * bb + 1], ql[ks], b2, b3);
            }
        }

        // ---- scale + bias (log2 domain) + causal mask
        const bool mask = (kt >= 2 * qt);
        const float* r0p = bph + (size_t)q_r0 * SEQ + k0 + 2 * (lane & 3);
        const float* r1p = bph + (size_t)q_r1 * SEQ + k0 + 2 * (lane & 3);
        #pragma unroll
        for (int nf = 0; nf < 8; ++nf) {
            float2 b0 = *reinterpret_cast<const float2*>(r0p + nf * 8);
            float2 b1 = *reinterpret_cast<const float2*>(r1p + nf * 8);
            float v0 = fmaf(sacc[nf][0], 0.18033688f, b0.x * 1.4426950f);
            float v1 = fmaf(sacc[nf][1], 0.18033688f, b0.y * 1.4426950f);
            float v2 = fmaf(sacc[nf][2], 0.18033688f, b1.x * 1.4426950f);
            float v3 = fmaf(sacc[nf][3], 0.18033688f, b1.y * 1.4426950f);
            if (mask) {
                const int kc = k0 + nf * 8 + 2 * (lane & 3);
                if (kc     > q_r0) v0 = -1e30f;
                if (kc + 1 > q_r0) v1 = -1e30f;
                if (kc     > q_r1) v2 = -1e30f;
                if (kc + 1 > q_r1) v3 = -1e30f;
            }
            sacc[nf][0] = v0; sacc[nf][1] = v1; sacc[nf][2] = v2; sacc[nf][3] = v3;
        }

        // ---- online softmax (base 2)
        float m0n = m0, m1n = m1;
        #pragma unroll
        for (int nf = 0; nf < 8; ++nf) {
            m0n = fmaxf(m0n, fmaxf(sacc[nf][0], sacc[nf][1]));
            m1n = fmaxf(m1n, fmaxf(sacc[nf][2], sacc[nf][3]));
        }
        m0n = fmaxf(m0n, __shfl_xor_sync(0xffffffffu, m0n, 1));
        m0n = fmaxf(m0n, __shfl_xor_sync(0xffffffffu, m0n, 2));
        m1n = fmaxf(m1n, __shfl_xor_sync(0xffffffffu, m1n, 1));
        m1n = fmaxf(m1n, __shfl_xor_sync(0xffffffffu, m1n, 2));
        const float c0 = exp2p(m0 - m0n), c1 = exp2p(m1 - m1n);
        m0 = m0n; m1 = m1n;
        l0 *= c0;  l1 *= c1;
        #pragma unroll
        for (int nf = 0; nf < 8; ++nf) {
            o[nf][0] *= c0; o[nf][1] *= c0;
            o[nf][2] *= c1; o[nf][3] *= c1;
        }

        uint32_t pA0[8], pA1[8], pL0[8], pL1[8];
        #pragma unroll
        for (int nf = 0; nf < 8; ++nf) {
            float p0 = exp2p(sacc[nf][0] - m0);
            float p1 = exp2p(sacc[nf][1] - m0);
            float p2 = exp2p(sacc[nf][2] - m1);
            float p3 = exp2p(sacc[nf][3] - m1);
            l0 += p0 + p1; l1 += p2 + p3;
            __half h0 = __float2half(p0), h1 = __float2half(p1);
            __half h2 = __float2half(p2), h3 = __float2half(p3);
            pA0[nf] = (uint32_t)__half_as_ushort(h0) | ((uint32_t)__half_as_ushort(h1) << 16);
            pA1[nf] = (uint32_t)__half_as_ushort(h2) | ((uint32_t)__half_as_ushort(h3) << 16);
            pL0[nf] = packh(p0 - __half2float(h0), p1 - __half2float(h1));
            pL1[nf] = packh(p2 - __half2float(h2), p3 - __half2float(h3));
        }

        // ---- O += P V  (P split, V single via ldmatrix.trans)
        #pragma unroll
        for (int ks = 0; ks < 4; ++ks) {
            uint32_t ah[4] = { pA0[2 * ks], pA1[2 * ks], pA0[2 * ks + 1], pA1[2 * ks + 1] };
            uint32_t al[4] = { pL0[2 * ks], pL1[2 * ks], pL0[2 * ks + 1], pL1[2 * ks + 1] };
            #pragma unroll
            for (int ng = 0; ng < 4; ++ng) {
                const uint32_t off =
                    ((ks * 16 + (lane & 7) + (lane & 8)) * RSA + ng * 16 + ((lane >> 4) << 3)) * 2;
                uint32_t h0, h1, h2, h3;
                LDMX4T(h0, h1, h2, h3, Vhu + off);
                MMA16816_2(o[2 * ng],     ah, h0, h1);
                MMA16816_2(o[2 * ng],     al, h0, h1);
                MMA16816_2(o[2 * ng + 1], ah, h2, h3);
                MMA16816_2(o[2 * ng + 1], al, h2, h3);
            }
        }

        if (kt + 1 < nt) store_tile((kt + 1) & 1);
        __syncthreads();
    }

    l0 += __shfl_xor_sync(0xffffffffu, l0, 1);
    l0 += __shfl_xor_sync(0xffffffffu, l0, 2);
    l1 += __shfl_xor_sync(0xffffffffu, l1, 1);
    l1 += __shfl_xor_sync(0xffffffffu, l1, 2);
    const float i0 = 1.f / l0, i1 = 1.f / l1;
    const size_t r0off = (size_t)(b * SEQ + q_r0) * DMODEL + h * DHEAD + 2 * (lane & 3);
    const size_t r1off = (size_t)(b * SEQ + q_r1) * DMODEL + h * DHEAD + 2 * (lane & 3);
    #pragma unroll
    for (int nf = 0; nf < 8; ++nf) {
        store_pair(AOh, AOl, r0off + nf * 8, o[nf][0] * i0, o[nf][1] * i0);
        store_pair(AOh, AOl, r1off + nf * 8, o[nf][2] * i1, o[nf][3] * i1);
    }
}

// ---------------------------------------------------------------------------
extern "C" void kernel_launch(void* const* d_in, const int* in_sizes, int n_in,
                              void* d_out, int out_size)
{
    const float* x     = (const float*)d_in[0];
    const float* basis = (const float*)d_in[1];
    const float* sq    = (const float*)d_in[2];
    const float* sk    = (const float*)d_in[3];
    const float* sv    = (const float*)d_in[4];
    const float* so    = (const float*)d_in[5];
    const float* bias  = (const float*)d_in[6];
    float*       out   = (float*)d_out;

    __half *Xh, *Xl, *BTh, *Bmh;
    __half *XBqh, *XBql, *XBkh, *XBkl, *XBvh, *XBvl;
    __half *AOh, *AOl, *O1h, *O1l;
    float *Qm, *Km, *Vm;
    cudaGetSymbolAddress((void**)&Xh,  g_Xh);  cudaGetSymbolAddress((void**)&Xl,  g_Xl);
    cudaGetSymbolAddress((void**)&BTh, g_BTh);
    cudaGetSymbolAddress((void**)&Bmh, g_Bmh);
    cudaGetSymbolAddress((void**)&XBqh, g_XBqh); cudaGetSymbolAddress((void**)&XBql, g_XBql);
    cudaGetSymbolAddress((void**)&XBkh, g_XBkh); cudaGetSymbolAddress((void**)&XBkl, g_XBkl);
    cudaGetSymbolAddress((void**)&XBvh, g_XBvh); cudaGetSymbolAddress((void**)&XBvl, g_XBvl);
    cudaGetSymbolAddress((void**)&AOh, g_AOh); cudaGetSymbolAddress((void**)&AOl, g_AOl);
    cudaGetSymbolAddress((void**)&O1h, g_O1h); cudaGetSymbolAddress((void**)&O1l, g_O1l);
    cudaGetSymbolAddress((void**)&Qm, g_Q);
    cudaGetSymbolAddress((void**)&Km, g_K);
    cudaGetSymbolAddress((void**)&Vm, g_V);

    cudaFuncSetAttribute(gemm_fp16x2<0>, cudaFuncAttributeMaxDynamicSharedMemorySize, SMEM_DYN);
    cudaFuncSetAttribute(gemm_fp16x2<1>, cudaFuncAttributeMaxDynamicSharedMemorySize, SMEM_DYN);
    cudaFuncSetAttribute(gemm_fp16x2<2>, cudaFuncAttributeMaxDynamicSharedMemorySize, SMEM_DYN);
    cudaFuncSetAttribute(attn_mma, cudaFuncAttributeMaxDynamicSharedMemorySize, ASMEM);

    // pre-split inputs
    split_plain<<<MROWS * DMODEL / 1024, 256>>>((const float4*)x, Xh, Xl);
    trunc_plain<<<DMODEL * DMODEL / 1024, 256>>>((const float4*)basis, Bmh);
    trans_trunc<<<dim3(32, 32), dim3(32, 8)>>>(basis, BTh);

    const dim3 gg(DMODEL / 128, MROWS / 128);
    // G1: XB = X @ basis, epilogue emits scale-fused pairs for q/k/v
    gemm_fp16x2<1><<<gg, 256, SMEM_DYN>>>(Xh, Xl, BTh, nullptr,
                                          sq, sk, sv,
                                          XBqh, XBql, XBkh, XBkl, XBvh, XBvl);
    // G2-4: Q/K/V fp32
    gemm_fp16x2<0><<<gg, 256, SMEM_DYN>>>(XBqh, XBql, Bmh, Qm,
                                          nullptr, nullptr, nullptr,
                                          nullptr, nullptr, nullptr, nullptr, nullptr, nullptr);
    gemm_fp16x2<0><<<gg, 256, SMEM_DYN>>>(XBkh, XBkl, Bmh, Km,
                                          nullptr, nullptr, nullptr,
                                          nullptr, nullptr, nullptr, nullptr, nullptr, nullptr);
    gemm_fp16x2<0><<<gg, 256, SMEM_DYN>>>(XBvh, XBvl, Bmh, Vm,
                                          nullptr, nullptr, nullptr,
                                          nullptr, nullptr, nullptr, nullptr, nullptr, nullptr);

    attn_mma<<<dim3(SEQ / 128, NHEADS, BATCH), 256, ASMEM>>>(Qm, Km, Vm, bias, AOh, AOl);

    // G5: O1 = AO @ basis, epilogue emits so-fused pair
    gemm_fp16x2<2><<<gg, 256, SMEM_DYN>>>(AOh, AOl, BTh, nullptr,
                                          so, nullptr, nullptr,
                                          O1h, O1l, nullptr, nullptr, nullptr, nullptr);
    // G6: out = O1s @ basis^T, fp32
    gemm_fp16x2<0><<<gg, 256, SMEM_DYN>>>(O1h, O1l, Bmh, out,
                                          nullptr, nullptr, nullptr,
                                          nullptr, nullptr, nullptr, nullptr, nullptr, nullptr);
}

// round 9
// speedup vs baseline: 1.3941x; 1.0331x over previous
#include <cuda_runtime.h>
#include <cuda_fp16.h>
#include <cstdint>
#include <cstddef>

#define SEQ    2048
#define BATCH  2
#define DMODEL 1024
#define NHEADS 16
#define DHEAD  64
#define MROWS  (BATCH*SEQ)

// ---------------- scratch (device globals; allocation-free rule) ------------
__device__ __half g_Xh [(size_t)MROWS*DMODEL], g_Xl [(size_t)MROWS*DMODEL];
__device__ __half g_BTh[(size_t)DMODEL*DMODEL];            // basis^T, fp16
__device__ __half g_Bmh[(size_t)DMODEL*DMODEL];            // basis, fp16
__device__ __half g_XBqh[(size_t)MROWS*DMODEL], g_XBql[(size_t)MROWS*DMODEL];
__device__ __half g_XBkh[(size_t)MROWS*DMODEL], g_XBkl[(size_t)MROWS*DMODEL];
__device__ __half g_XBvh[(size_t)MROWS*DMODEL], g_XBvl[(size_t)MROWS*DMODEL];
__device__ __half g_AOh[(size_t)MROWS*DMODEL],  g_AOl[(size_t)MROWS*DMODEL];
__device__ __half g_O1h[(size_t)MROWS*DMODEL],  g_O1l[(size_t)MROWS*DMODEL];
__device__ __half g_Qh[(size_t)MROWS*DMODEL], g_Ql[(size_t)MROWS*DMODEL];
__device__ __half g_Kh[(size_t)MROWS*DMODEL], g_Vh[(size_t)MROWS*DMODEL];

// ---------------------------------------------------------------------------
__device__ __forceinline__ uint32_t smem_u32(const void* p) {
    uint32_t a;
    asm("{ .reg .u64 t; cvta.to.shared.u64 t, %1; cvt.u32.u64 %0, t; }"
        : "=r"(a) : "l"(p));
    return a;
}

#define LDMX4(r0, r1, r2, r3, addr) \
    asm volatile("ldmatrix.sync.aligned.m8n8.x4.shared.b16 {%0,%1,%2,%3}, [%4];" \
                 : "=r"(r0), "=r"(r1), "=r"(r2), "=r"(r3) : "r"(addr))

#define LDMX4T(r0, r1, r2, r3, addr) \
    asm volatile("ldmatrix.sync.aligned.m8n8.x4.trans.shared.b16 {%0,%1,%2,%3}, [%4];" \
                 : "=r"(r0), "=r"(r1), "=r"(r2), "=r"(r3) : "r"(addr))

#define MMA16816_2(d, a, b0r, b1r) \
    asm volatile("mma.sync.aligned.m16n8k16.row.col.f32.f16.f16.f32 " \
                 "{%0,%1,%2,%3}, {%4,%5,%6,%7}, {%8,%9}, {%0,%1,%2,%3};" \
                 : "+f"((d)[0]), "+f"((d)[1]), "+f"((d)[2]), "+f"((d)[3]) \
                 : "r"((a)[0]), "r"((a)[1]), "r"((a)[2]), "r"((a)[3]), \
                   "r"(b0r), "r"(b1r))

#define CPASYNC16(dst, src) \
    asm volatile("cp.async.cg.shared.global [%0], [%1], 16;" \
                 :: "r"(dst), "l"(src))
#define CPCOMMIT()  asm volatile("cp.async.commit_group;" ::: "memory")
#define CPWAIT(n)   asm volatile("cp.async.wait_group %0;" :: "n"(n) : "memory")

// XOR swizzle for 64B rows (GEMM tiles)
__device__ __forceinline__ uint32_t swz(uint32_t o) {
    return o ^ (((o >> 7) & 3u) << 4);
}

__device__ __forceinline__ uint32_t packh(float a, float b) {
    __half x = __float2half(a), y = __float2half(b);
    return (uint32_t)__half_as_ushort(x) | ((uint32_t)__half_as_ushort(y) << 16);
}

__device__ __forceinline__ void split_store(void* hp, void* lp, float4 v) {
    __half h0 = __float2half(v.x), h1 = __float2half(v.y);
    __half h2 = __float2half(v.z), h3 = __float2half(v.w);
    uint2 hu, lu;
    hu.x = (uint32_t)__half_as_ushort(h0) | ((uint32_t)__half_as_ushort(h1) << 16);
    hu.y = (uint32_t)__half_as_ushort(h2) | ((uint32_t)__half_as_ushort(h3) << 16);
    lu.x = packh(v.x - __half2float(h0), v.y - __half2float(h1));
    lu.y = packh(v.z - __half2float(h2), v.w - __half2float(h3));
    *reinterpret_cast<uint2*>(hp) = hu;
    *reinterpret_cast<uint2*>(lp) = lu;
}

__device__ __forceinline__ void trunc_store(void* hp, float4 v) {
    uint2 hu;
    hu.x = packh(v.x, v.y);
    hu.y = packh(v.z, v.w);
    *reinterpret_cast<uint2*>(hp) = hu;
}

__device__ __forceinline__ void store_pair(__half* Ph, __half* Pl,
                                           size_t off, float a, float b) {
    __half h0 = __float2half(a), h1 = __float2half(b);
    uint32_t hu = (uint32_t)__half_as_ushort(h0) | ((uint32_t)__half_as_ushort(h1) << 16);
    uint32_t lu = packh(a - __half2float(h0), b - __half2float(h1));
    *reinterpret_cast<uint32_t*>(Ph + off) = hu;
    *reinterpret_cast<uint32_t*>(Pl + off) = lu;
}

// 2^y via FMA-pipe polynomial (no MUFU)
__device__ __forceinline__ float exp2p(float y) {
    y = fmaxf(y, -120.f);
    float t = y + 12582912.f;
    int   n = (__float_as_int(t) & 0x7FFFFF) - 0x400000;
    float f = y - (t - 12582912.f);
    float p = 1.3333558146e-3f;
    p = fmaf(p, f, 9.6181291076e-3f);
    p = fmaf(p, f, 5.5504108664e-2f);
    p = fmaf(p, f, 2.4022650695e-1f);
    p = fmaf(p, f, 6.9314718056e-1f);
    p = fmaf(p, f, 1.0f);
    return __int_as_float(__float_as_int(p) + (n << 23));
}

// ---------------------------------------------------------------------------
// Pre-split helpers
// ---------------------------------------------------------------------------
__global__ void split_plain(const float4* __restrict__ in,
                            __half* __restrict__ h, __half* __restrict__ l) {
    size_t i = (size_t)blockIdx.x * 256 + threadIdx.x;
    float4 v = in[i];
    split_store(h + 4 * i, l + 4 * i, v);
}

__global__ void trunc_plain(const float4* __restrict__ in, __half* __restrict__ h) {
    size_t i = (size_t)blockIdx.x * 256 + threadIdx.x;
    trunc_store(h + 4 * i, in[i]);
}

__global__ void trans_trunc(const float* __restrict__ in, __half* __restrict__ oh) {
    __shared__ float t[32][33];
    int bx = blockIdx.x * 32, by = blockIdx.y * 32;
    #pragma unroll
    for (int i = 0; i < 32; i += 8)
        t[threadIdx.y + i][threadIdx.x] = in[(size_t)(by + threadIdx.y + i) * DMODEL + bx + threadIdx.x];
    __syncthreads();
    #pragma unroll
    for (int i = 0; i < 32; i += 8) {
        float v = t[threadIdx.x][threadIdx.y + i];
        oh[(size_t)(bx + threadIdx.y + i) * DMODEL + by + threadIdx.x] = __float2half(v);
    }
}

// ---------------------------------------------------------------------------
// fp16x2 mma.sync GEMM.  EPI: 0=fp32 C; 1=three scaled pairs; 2=one scaled
// pair; 3=one plain pair; 4=one plain single-fp16.
// Tile 128x128, BK=32, 4-stage cp.async, XOR-swizzled 64B rows, 2 CTAs/SM.
// ---------------------------------------------------------------------------
static constexpr int STAGE_B  = 24576;
static constexpr int SMEM_DYN = 4 * STAGE_B;     // 98304

template<int EPI>
__global__ __launch_bounds__(256, 2)
void gemm_fp16x2(const __half* __restrict__ Ah, const __half* __restrict__ Al,
                 const __half* __restrict__ Bh,
                 float* __restrict__ C,
                 const float* __restrict__ s0, const float* __restrict__ s1,
                 const float* __restrict__ s2,
                 __half* __restrict__ P0h, __half* __restrict__ P0l,
                 __half* __restrict__ P1h, __half* __restrict__ P1l,
                 __half* __restrict__ P2h, __half* __restrict__ P2l)
{
    extern __shared__ char smem[];
    const int tid  = threadIdx.x;
    const int lane = tid & 31;
    const int wid  = tid >> 5;
    const int bm   = blockIdx.y * 128;
    const int bn   = blockIdx.x * 128;
    const int wm0  = (wid & 3) * 32;
    const int wn0  = (wid >> 2) * 64;
    const uint32_t sbase = smem_u32(smem);

    const int crow = tid >> 2;            // 0..63
    const int cchk = (tid & 3) * 16;

    const char* gA_h = (const char*)Ah + (size_t)(bm + crow) * 2048 + cchk;
    const char* gA_l = (const char*)Al + (size_t)(bm + crow) * 2048 + cchk;
    const char* gB_h = (const char*)Bh + (size_t)(bn + crow) * 2048 + cchk;

    const uint32_t so1 = swz((uint32_t)(crow * 64 + cchk));
    const uint32_t so2 = swz((uint32_t)(crow * 64 + cchk) + 4096u);

    auto issue_stage = [&](int c, int s) {
        const size_t k0b = (size_t)c * 64;
        const uint32_t st = sbase + (uint32_t)s * STAGE_B;
        CPASYNC16(st + so1,          gA_h + k0b);
        CPASYNC16(st + so2,          gA_h + k0b + (size_t)64 * 2048);
        CPASYNC16(st + 8192u  + so1, gA_l + k0b);
        CPASYNC16(st + 8192u  + so2, gA_l + k0b + (size_t)64 * 2048);
        CPASYNC16(st + 16384u + so1, gB_h + k0b);
        CPASYNC16(st + 16384u + so2, gB_h + k0b + (size_t)64 * 2048);
        CPCOMMIT();
    };

    float acc[2][8][4];
    #pragma unroll
    for (int i = 0; i < 2; ++i)
        #pragma unroll
        for (int j = 0; j < 8; ++j)
            #pragma unroll
            for (int q = 0; q < 4; ++q) acc[i][j][q] = 0.f;

    uint32_t aoff[2], boff[4];
    #pragma unroll
    for (int mt = 0; mt < 2; ++mt)
        aoff[mt] = (uint32_t)((wm0 + mt * 16 + (lane & 15)) * 64 + ((lane >> 4) << 4));
    #pragma unroll
    for (int bb = 0; bb < 4; ++bb)
        boff[bb] = (uint32_t)((wn0 + bb * 16 + (lane & 7) + ((lane >> 4) << 3)) * 64 + ((lane & 8) << 1));

    auto compute = [&](int s) {
        const uint32_t st = sbase + (uint32_t)s * STAGE_B;
        #pragma unroll
        for (int ks = 0; ks < 2; ++ks) {
            const uint32_t kb = ks * 32u;
            uint32_t ah[2][4], al[2][4], bf[4][4];
            #pragma unroll
            for (int mt = 0; mt < 2; ++mt) {
                const uint32_t off = swz(aoff[mt] + kb);
                LDMX4(ah[mt][0], ah[mt][1], ah[mt][2], ah[mt][3], st + off);
                LDMX4(al[mt][0], al[mt][1], al[mt][2], al[mt][3], st + 8192u + off);
            }
            #pragma unroll
            for (int bb = 0; bb < 4; ++bb) {
                const uint32_t off = swz(boff[bb] + kb);
                LDMX4(bf[bb][0], bf[bb][1], bf[bb][2], bf[bb][3], st + 16384u + off);
            }
            // pass 1: all hi-A MMAs (dependent acc updates 16 apart)
            #pragma unroll
            for (int bb = 0; bb < 4; ++bb)
                #pragma unroll
                for (int mt = 0; mt < 2; ++mt) {
                    MMA16816_2(acc[mt][2 * bb],     ah[mt], bf[bb][0], bf[bb][1]);
                    MMA16816_2(acc[mt][2 * bb + 1], ah[mt], bf[bb][2], bf[bb][3]);
                }
            // pass 2: all lo-A MMAs
            #pragma unroll
            for (int bb = 0; bb < 4; ++bb)
                #pragma unroll
                for (int mt = 0; mt < 2; ++mt) {
                    MMA16816_2(acc[mt][2 * bb],     al[mt], bf[bb][0], bf[bb][1]);
                    MMA16816_2(acc[mt][2 * bb + 1], al[mt], bf[bb][2], bf[bb][3]);
                }
        }
    };

    issue_stage(0, 0);
    issue_stage(1, 1);
    issue_stage(2, 2);

    for (int c = 0; c < 32; ++c) {
        if (c <= 29)      { CPWAIT(2); }
        else if (c == 30) { CPWAIT(1); }
        else              { CPWAIT(0); }
        __syncthreads();
        if (c + 3 < 32) issue_stage(c + 3, (c + 3) & 3);
        compute(c & 3);
    }

    // ---- epilogue
    #pragma unroll
    for (int mt = 0; mt < 2; ++mt) {
        const int m = bm + wm0 + mt * 16 + (lane >> 2);
        #pragma unroll
        for (int nf = 0; nf < 8; ++nf) {
            const int n = bn + wn0 + nf * 8 + (lane & 3) * 2;
            const size_t o0 = (size_t)m * DMODEL + n;
            const size_t o1 = (size_t)(m + 8) * DMODEL + n;
            if (EPI == 0) {
                float2 v0 = {acc[mt][nf][0], acc[mt][nf][1]};
                float2 v1 = {acc[mt][nf][2], acc[mt][nf][3]};
                *reinterpret_cast<float2*>(C + o0) = v0;
                *reinterpret_cast<float2*>(C + o1) = v1;
            } else if (EPI == 3) {
                store_pair(P0h, P0l, o0, acc[mt][nf][0], acc[mt][nf][1]);
                store_pair(P0h, P0l, o1, acc[mt][nf][2], acc[mt][nf][3]);
            } else if (EPI == 4) {
                *reinterpret_cast<uint32_t*>(P0h + o0) = packh(acc[mt][nf][0], acc[mt][nf][1]);
                *reinterpret_cast<uint32_t*>(P0h + o1) = packh(acc[mt][nf][2], acc[mt][nf][3]);
            } else {
                float2 sc0 = *reinterpret_cast<const float2*>(s0 + n);
                store_pair(P0h, P0l, o0, acc[mt][nf][0] * sc0.x, acc[mt][nf][1] * sc0.y);
                store_pair(P0h, P0l, o1, acc[mt][nf][2] * sc0.x, acc[mt][nf][3] * sc0.y);
                if (EPI == 1) {
                    float2 sc1 = *reinterpret_cast<const float2*>(s1 + n);
                    float2 sc2 = *reinterpret_cast<const float2*>(s2 + n);
                    store_pair(P1h, P1l, o0, acc[mt][nf][0] * sc1.x, acc[mt][nf][1] * sc1.y);
                    store_pair(P1h, P1l, o1, acc[mt][nf][2] * sc1.x, acc[mt][nf][3] * sc1.y);
                    store_pair(P2h, P2l, o0, acc[mt][nf][0] * sc2.x, acc[mt][nf][1] * sc2.y);
                    store_pair(P2h, P2l, o1, acc[mt][nf][2] * sc2.x, acc[mt][nf][3] * sc2.y);
                }
            }
        }
    }
}

// ---------------------------------------------------------------------------
// fp16 flash attention, all-fp16 inputs (Qh/Ql pair, Kh/Vh single).
// K/V staged by 3-stage cp.async pipeline; Q copied smem-direct.
// smem (fp16 elems): Qh[0..9216) Ql[9216..18432) stages at 18432 + s*9216
//   each stage: K 64x72 (4608) then V 64x72 (4608). Rows padded to 72 (144B).
// ---------------------------------------------------------------------------
static constexpr int RSA    = 72;
static constexpr int QMAT_E = 128 * RSA;           // 9216 elems
static constexpr int STG_E  = 2 * 64 * RSA;        // 9216 elems (K+V)
static constexpr int ASMEM  = (2 * QMAT_E + 3 * STG_E) * 2;   // 92160 bytes

__global__ __launch_bounds__(256, 1)
void attn_mma(const __half* __restrict__ Qh, const __half* __restrict__ Ql,
              const __half* __restrict__ Kh, const __half* __restrict__ Vh,
              const float* __restrict__ bias,
              __half* __restrict__ AOh, __half* __restrict__ AOl)
{
    extern __shared__ __half asmem[];
    const int tid  = threadIdx.x;
    const int lane = tid & 31;
    const int w    = tid >> 5;
    const int qt   = (int)gridDim.x - 1 - (int)blockIdx.x;   // heavy first
    const int h    = blockIdx.y;
    const int b    = blockIdx.z;
    const int q0   = qt * 128;
    const uint32_t sbase = smem_u32(asmem);
    const int nt   = 2 * qt + 2;

    // cp.async geometry for K/V: row = tid>>2 (0..63), 32B segment = (tid&3)*32
    const int krow = tid >> 2;
    const int kseg = (tid & 3) * 32;                 // bytes within 128B row
    const char* gK = (const char*)(Kh + (size_t)(b * SEQ + krow) * DMODEL + h * DHEAD) + kseg;
    const char* gV = (const char*)(Vh + (size_t)(b * SEQ + krow) * DMODEL + h * DHEAD) + kseg;
    const uint32_t kvoff = (uint32_t)(krow * 144 + kseg);

    auto issue_kv = [&](int kt, int s) {
        const size_t gofs = (size_t)kt * 64 * 2048;  // 64 rows * 2048B
        const uint32_t st = sbase + (uint32_t)(2 * QMAT_E + s * STG_E) * 2;
        CPASYNC16(st + kvoff,                 gK + gofs);
        CPASYNC16(st + kvoff + 16,            gK + gofs + 16);
        CPASYNC16(st + 9216u + kvoff,         gV + gofs);
        CPASYNC16(st + 9216u + kvoff + 16,    gV + gofs + 16);
        CPCOMMIT();
    };

    issue_kv(0, 0);
    issue_kv(1, 1);

    // ---- copy Q (hi & lo) gmem->smem (16B chunks)
    {
        const __half* Qbh = Qh + (size_t)(b * SEQ + q0) * DMODEL + h * DHEAD;
        const __half* Qbl = Ql + (size_t)(b * SEQ + q0) * DMODEL + h * DHEAD;
        #pragma unroll
        for (int i = 0; i < 8; ++i) {
            int idx = tid + i * 256;                 // 0..2047
            int mat = idx >> 10;                     // 0=h, 1=l
            int r   = (idx >> 3) & 127;
            int c16 = idx & 7;
            const __half* src = (mat ? Qbl : Qbh) + (size_t)r * DMODEL + c16 * 8;
            uint4 v = *reinterpret_cast<const uint4*>(src);
            *reinterpret_cast<uint4*>(asmem + mat * QMAT_E + r * RSA + c16 * 8) = v;
        }
    }
    __syncthreads();

    uint32_t qfh[4][4], qfl[4][4];
    #pragma unroll
    for (int ks = 0; ks < 4; ++ks) {
        const uint32_t off = ((w * 16 + (lane & 15)) * RSA + ks * 16 + ((lane >> 4) << 3)) * 2;
        LDMX4(qfh[ks][0], qfh[ks][1], qfh[ks][2], qfh[ks][3], sbase + off);
        LDMX4(qfl[ks][0], qfl[ks][1], qfl[ks][2], qfl[ks][3], sbase + QMAT_E * 2 + off);
    }

    float m0 = -1e30f, m1 = -1e30f, l0 = 0.f, l1 = 0.f;
    float o[8][4];
    #pragma unroll
    for (int j = 0; j < 8; ++j)
        #pragma unroll
        for (int q = 0; q < 4; ++q) o[j][q] = 0.f;

    const int q_r0 = q0 + w * 16 + (lane >> 2);
    const int q_r1 = q_r0 + 8;
    const float* bph = bias + (size_t)h * SEQ * SEQ;

    for (int kt = 0; kt < nt; ++kt) {
        const int k0 = kt * 64;
        if (kt + 1 < nt) { CPWAIT(1); } else { CPWAIT(0); }
        __syncthreads();
        if (kt + 2 < nt) issue_kv(kt + 2, (kt + 2) % 3);

        const uint32_t Khu = sbase + (uint32_t)(2 * QMAT_E + (kt % 3) * STG_E) * 2;
        const uint32_t Vhu = Khu + 9216u;

        // ---- S = Q K^T  (Q split, K single)
        float sacc[8][4];
        #pragma unroll
        for (int j = 0; j < 8; ++j)
            #pragma unroll
            for (int q = 0; q < 4; ++q) sacc[j][q] = 0.f;
        #pragma unroll
        for (int ks = 0; ks < 4; ++ks) {
            #pragma unroll
            for (int bb = 0; bb < 4; ++bb) {
                const uint32_t off =
                    ((bb * 16 + (lane & 7) + ((lane >> 4) << 3)) * RSA + ks * 16 + (lane & 8)) * 2;
                uint32_t b0, b1, b2, b3;
                LDMX4(b0, b1, b2, b3, Khu + off);
                MMA16816_2(sacc[2 * bb],     qfh[ks], b0, b1);
                MMA16816_2(sacc[2 * bb],     qfl[ks], b0, b1);
                MMA16816_2(sacc[2 * bb + 1], qfh[ks], b2, b3);
                MMA16816_2(sacc[2 * bb + 1], qfl[ks], b2, b3);
            }
        }

        // ---- scale + bias (log2 domain) + causal mask
        const bool mask = (kt >= 2 * qt);
        const float* r0p = bph + (size_t)q_r0 * SEQ + k0 + 2 * (lane & 3);
        const float* r1p = bph + (size_t)q_r1 * SEQ + k0 + 2 * (lane & 3);
        #pragma unroll
        for (int nf = 0; nf < 8; ++nf) {
            float2 b0 = *reinterpret_cast<const float2*>(r0p + nf * 8);
            float2 b1 = *reinterpret_cast<const float2*>(r1p + nf * 8);
            float v0 = fmaf(sacc[nf][0], 0.18033688f, b0.x * 1.4426950f);
            float v1 = fmaf(sacc[nf][1], 0.18033688f, b0.y * 1.4426950f);
            float v2 = fmaf(sacc[nf][2], 0.18033688f, b1.x * 1.4426950f);
            float v3 = fmaf(sacc[nf][3], 0.18033688f, b1.y * 1.4426950f);
            if (mask) {
                const int kc = k0 + nf * 8 + 2 * (lane & 3);
                if (kc     > q_r0) v0 = -1e30f;
                if (kc + 1 > q_r0) v1 = -1e30f;
                if (kc     > q_r1) v2 = -1e30f;
                if (kc + 1 > q_r1) v3 = -1e30f;
            }
            sacc[nf][0] = v0; sacc[nf][1] = v1; sacc[nf][2] = v2; sacc[nf][3] = v3;
        }

        // ---- online softmax (base 2)
        float m0n = m0, m1n = m1;
        #pragma unroll
        for (int nf = 0; nf < 8; ++nf) {
            m0n = fmaxf(m0n, fmaxf(sacc[nf][0], sacc[nf][1]));
            m1n = fmaxf(m1n, fmaxf(sacc[nf][2], sacc[nf][3]));
        }
        m0n = fmaxf(m0n, __shfl_xor_sync(0xffffffffu, m0n, 1));
        m0n = fmaxf(m0n, __shfl_xor_sync(0xffffffffu, m0n, 2));
        m1n = fmaxf(m1n, __shfl_xor_sync(0xffffffffu, m1n, 1));
        m1n = fmaxf(m1n, __shfl_xor_sync(0xffffffffu, m1n, 2));
        const float c0 = exp2p(m0 - m0n), c1 = exp2p(m1 - m1n);
        m0 = m0n; m1 = m1n;
        l0 *= c0;  l1 *= c1;
        #pragma unroll
        for (int nf = 0; nf < 8; ++nf) {
            o[nf][0] *= c0; o[nf][1] *= c0;
            o[nf][2] *= c1; o[nf][3] *= c1;
        }

        uint32_t pA0[8], pA1[8], pL0[8], pL1[8];
        #pragma unroll
        for (int nf = 0; nf < 8; ++nf) {
            float p0 = exp2p(sacc[nf][0] - m0);
            float p1 = exp2p(sacc[nf][1] - m0);
            float p2 = exp2p(sacc[nf][2] - m1);
            float p3 = exp2p(sacc[nf][3] - m1);
            l0 += p0 + p1; l1 += p2 + p3;
            __half h0 = __float2half(p0), h1 = __float2half(p1);
            __half h2 = __float2half(p2), h3 = __float2half(p3);
            pA0[nf] = (uint32_t)__half_as_ushort(h0) | ((uint32_t)__half_as_ushort(h1) << 16);
            pA1[nf] = (uint32_t)__half_as_ushort(h2) | ((uint32_t)__half_as_ushort(h3) << 16);
            pL0[nf] = packh(p0 - __half2float(h0), p1 - __half2float(h1));
            pL1[nf] = packh(p2 - __half2float(h2), p3 - __half2float(h3));
        }

        // ---- O += P V  (P split, V single via ldmatrix.trans)
        #pragma unroll
        for (int ks = 0; ks < 4; ++ks) {
            uint32_t ah[4] = { pA0[2 * ks], pA1[2 * ks], pA0[2 * ks + 1], pA1[2 * ks + 1] };
            uint32_t al[4] = { pL0[2 * ks], pL1[2 * ks], pL0[2 * ks + 1], pL1[2 * ks + 1] };
            #pragma unroll
            for (int ng = 0; ng < 4; ++ng) {
                const uint32_t off =
                    ((ks * 16 + (lane & 7) + (lane & 8)) * RSA + ng * 16 + ((lane >> 4) << 3)) * 2;
                uint32_t h0, h1, h2, h3;
                LDMX4T(h0, h1, h2, h3, Vhu + off);
                MMA16816_2(o[2 * ng],     ah, h0, h1);
                MMA16816_2(o[2 * ng],     al, h0, h1);
                MMA16816_2(o[2 * ng + 1], ah, h2, h3);
                MMA16816_2(o[2 * ng + 1], al, h2, h3);
            }
        }
    }

    l0 += __shfl_xor_sync(0xffffffffu, l0, 1);
    l0 += __shfl_xor_sync(0xffffffffu, l0, 2);
    l1 += __shfl_xor_sync(0xffffffffu, l1, 1);
    l1 += __shfl_xor_sync(0xffffffffu, l1, 2);
    const float i0 = 1.f / l0, i1 = 1.f / l1;
    const size_t r0off = (size_t)(b * SEQ + q_r0) * DMODEL + h * DHEAD + 2 * (lane & 3);
    const size_t r1off = (size_t)(b * SEQ + q_r1) * DMODEL + h * DHEAD + 2 * (lane & 3);
    #pragma unroll
    for (int nf = 0; nf < 8; ++nf) {
        store_pair(AOh, AOl, r0off + nf * 8, o[nf][0] * i0, o[nf][1] * i0);
        store_pair(AOh, AOl, r1off + nf * 8, o[nf][2] * i1, o[nf][3] * i1);
    }
}

// ---------------------------------------------------------------------------
extern "C" void kernel_launch(void* const* d_in, const int* in_sizes, int n_in,
                              void* d_out, int out_size)
{
    const float* x     = (const float*)d_in[0];
    const float* basis = (const float*)d_in[1];
    const float* sq    = (const float*)d_in[2];
    const float* sk    = (const float*)d_in[3];
    const float* sv    = (const float*)d_in[4];
    const float* so    = (const float*)d_in[5];
    const float* bias  = (const float*)d_in[6];
    float*       out   = (float*)d_out;

    __half *Xh, *Xl, *BTh, *Bmh;
    __half *XBqh, *XBql, *XBkh, *XBkl, *XBvh, *XBvl;
    __half *AOh, *AOl, *O1h, *O1l, *Qh, *Ql, *Kh, *Vh;
    cudaGetSymbolAddress((void**)&Xh,  g_Xh);  cudaGetSymbolAddress((void**)&Xl,  g_Xl);
    cudaGetSymbolAddress((void**)&BTh, g_BTh);
    cudaGetSymbolAddress((void**)&Bmh, g_Bmh);
    cudaGetSymbolAddress((void**)&XBqh, g_XBqh); cudaGetSymbolAddress((void**)&XBql, g_XBql);
    cudaGetSymbolAddress((void**)&XBkh, g_XBkh); cudaGetSymbolAddress((void**)&XBkl, g_XBkl);
    cudaGetSymbolAddress((void**)&XBvh, g_XBvh); cudaGetSymbolAddress((void**)&XBvl, g_XBvl);
    cudaGetSymbolAddress((void**)&AOh, g_AOh); cudaGetSymbolAddress((void**)&AOl, g_AOl);
    cudaGetSymbolAddress((void**)&O1h, g_O1h); cudaGetSymbolAddress((void**)&O1l, g_O1l);
    cudaGetSymbolAddress((void**)&Qh, g_Qh); cudaGetSymbolAddress((void**)&Ql, g_Ql);
    cudaGetSymbolAddress((void**)&Kh, g_Kh); cudaGetSymbolAddress((void**)&Vh, g_Vh);

    cudaFuncSetAttribute(gemm_fp16x2<0>, cudaFuncAttributeMaxDynamicSharedMemorySize, SMEM_DYN);
    cudaFuncSetAttribute(gemm_fp16x2<1>, cudaFuncAttributeMaxDynamicSharedMemorySize, SMEM_DYN);
    cudaFuncSetAttribute(gemm_fp16x2<2>, cudaFuncAttributeMaxDynamicSharedMemorySize, SMEM_DYN);
    cudaFuncSetAttribute(gemm_fp16x2<3>, cudaFuncAttributeMaxDynamicSharedMemorySize, SMEM_DYN);
    cudaFuncSetAttribute(gemm_fp16x2<4>, cudaFuncAttributeMaxDynamicSharedMemorySize, SMEM_DYN);
    cudaFuncSetAttribute(attn_mma, cudaFuncAttributeMaxDynamicSharedMemorySize, ASMEM);

    // pre-split inputs
    split_plain<<<MROWS * DMODEL / 1024, 256>>>((const float4*)x, Xh, Xl);
    trunc_plain<<<DMODEL * DMODEL / 1024, 256>>>((const float4*)basis, Bmh);
    trans_trunc<<<dim3(32, 32), dim3(32, 8)>>>(basis, BTh);

    const dim3 gg(DMODEL / 128, MROWS / 128);
    // G1: XB = X @ basis, emits scale-fused pairs for q/k/v
    gemm_fp16x2<1><<<gg, 256, SMEM_DYN>>>(Xh, Xl, BTh, nullptr,
                                          sq, sk, sv,
                                          XBqh, XBql, XBkh, XBkl, XBvh, XBvl);
    // G2: Q as fp16 pair
    gemm_fp16x2<3><<<gg, 256, SMEM_DYN>>>(XBqh, XBql, Bmh, nullptr,
                                          nullptr, nullptr, nullptr,
                                          Qh, Ql, nullptr, nullptr, nullptr, nullptr);
    // G3/G4: K/V as fp16 single
    gemm_fp16x2<4><<<gg, 256, SMEM_DYN>>>(XBkh, XBkl, Bmh, nullptr,
                                          nullptr, nullptr, nullptr,
                                          Kh, nullptr, nullptr, nullptr, nullptr, nullptr);
    gemm_fp16x2<4><<<gg, 256, SMEM_DYN>>>(XBvh, XBvl, Bmh, nullptr,
                                          nullptr, nullptr, nullptr,
                                          Vh, nullptr, nullptr, nullptr, nullptr, nullptr);

    attn_mma<<<dim3(SEQ / 128, NHEADS, BATCH), 256, ASMEM>>>(Qh, Ql, Kh, Vh, bias, AOh, AOl);

    // G5: O1 = AO @ basis, so-fused pair
    gemm_fp16x2<2><<<gg, 256, SMEM_DYN>>>(AOh, AOl, BTh, nullptr,
                                          so, nullptr, nullptr,
                                          O1h, O1l, nullptr, nullptr, nullptr, nullptr);
    // G6: out = O1s @ basis^T, fp32
    gemm_fp16x2<0><<<gg, 256, SMEM_DYN>>>(O1h, O1l, Bmh, out,
                                          nullptr, nullptr, nullptr,
                                          nullptr, nullptr, nullptr, nullptr, nullptr, nullptr);
}

// round 10
// speedup vs baseline: 1.6276x; 1.1675x over previous
#include <cuda_runtime.h>
#include <cuda_fp16.h>
#include <cstdint>
#include <cstddef>

#define SEQ    2048
#define BATCH  2
#define DMODEL 1024
#define NHEADS 16
#define DHEAD  64
#define MROWS  (BATCH*SEQ)

// ---------------- scratch (device globals; allocation-free rule) ------------
__device__ __half g_Xh [(size_t)MROWS*DMODEL];
__device__ __half g_BTh[(size_t)DMODEL*DMODEL];            // basis^T, fp16
__device__ __half g_Bmh[(size_t)DMODEL*DMODEL];            // basis, fp16
__device__ __half g_XBq[(size_t)MROWS*DMODEL];
__device__ __half g_XBk[(size_t)MROWS*DMODEL];
__device__ __half g_XBv[(size_t)MROWS*DMODEL];
__device__ __half g_AOh[(size_t)MROWS*DMODEL];
__device__ __half g_O1h[(size_t)MROWS*DMODEL];
__device__ __half g_Qh[(size_t)MROWS*DMODEL];
__device__ __half g_Kh[(size_t)MROWS*DMODEL], g_Vh[(size_t)MROWS*DMODEL];

// ---------------------------------------------------------------------------
__device__ __forceinline__ uint32_t smem_u32(const void* p) {
    uint32_t a;
    asm("{ .reg .u64 t; cvta.to.shared.u64 t, %1; cvt.u32.u64 %0, t; }"
        : "=r"(a) : "l"(p));
    return a;
}

#define LDMX4(r0, r1, r2, r3, addr) \
    asm volatile("ldmatrix.sync.aligned.m8n8.x4.shared.b16 {%0,%1,%2,%3}, [%4];" \
                 : "=r"(r0), "=r"(r1), "=r"(r2), "=r"(r3) : "r"(addr))

#define LDMX4T(r0, r1, r2, r3, addr) \
    asm volatile("ldmatrix.sync.aligned.m8n8.x4.trans.shared.b16 {%0,%1,%2,%3}, [%4];" \
                 : "=r"(r0), "=r"(r1), "=r"(r2), "=r"(r3) : "r"(addr))

#define MMA16816_2(d, a, b0r, b1r) \
    asm volatile("mma.sync.aligned.m16n8k16.row.col.f32.f16.f16.f32 " \
                 "{%0,%1,%2,%3}, {%4,%5,%6,%7}, {%8,%9}, {%0,%1,%2,%3};" \
                 : "+f"((d)[0]), "+f"((d)[1]), "+f"((d)[2]), "+f"((d)[3]) \
                 : "r"((a)[0]), "r"((a)[1]), "r"((a)[2]), "r"((a)[3]), \
                   "r"(b0r), "r"(b1r))

#define CPASYNC16(dst, src) \
    asm volatile("cp.async.cg.shared.global [%0], [%1], 16;" \
                 :: "r"(dst), "l"(src))
#define CPCOMMIT()  asm volatile("cp.async.commit_group;" ::: "memory")
#define CPWAIT(n)   asm volatile("cp.async.wait_group %0;" :: "n"(n) : "memory")

// XOR swizzle for 128B rows: chunk(0..7) ^= row&7 -> conflict-free ldmatrix
__device__ __forceinline__ uint32_t swz128(uint32_t o) {
    return o ^ (((o >> 7) & 7u) << 4);
}

__device__ __forceinline__ uint32_t packh(float a, float b) {
    __half x = __float2half(a), y = __float2half(b);
    return (uint32_t)__half_as_ushort(x) | ((uint32_t)__half_as_ushort(y) << 16);
}

__device__ __forceinline__ void trunc_store(void* hp, float4 v) {
    uint2 hu;
    hu.x = packh(v.x, v.y);
    hu.y = packh(v.z, v.w);
    *reinterpret_cast<uint2*>(hp) = hu;
}

// 2^y via FMA-pipe polynomial (no MUFU)
__device__ __forceinline__ float exp2p(float y) {
    y = fmaxf(y, -120.f);
    float t = y + 12582912.f;
    int   n = (__float_as_int(t) & 0x7FFFFF) - 0x400000;
    float f = y - (t - 12582912.f);
    float p = 1.3333558146e-3f;
    p = fmaf(p, f, 9.6181291076e-3f);
    p = fmaf(p, f, 5.5504108664e-2f);
    p = fmaf(p, f, 2.4022650695e-1f);
    p = fmaf(p, f, 6.9314718056e-1f);
    p = fmaf(p, f, 1.0f);
    return __int_as_float(__float_as_int(p) + (n << 23));
}

// ---------------------------------------------------------------------------
// Pre-truncate helpers
// ---------------------------------------------------------------------------
__global__ void trunc_plain(const float4* __restrict__ in, __half* __restrict__ h) {
    size_t i = (size_t)blockIdx.x * 256 + threadIdx.x;
    trunc_store(h + 4 * i, in[i]);
}

__global__ void trans_trunc(const float* __restrict__ in, __half* __restrict__ oh) {
    __shared__ float t[32][33];
    int bx = blockIdx.x * 32, by = blockIdx.y * 32;
    #pragma unroll
    for (int i = 0; i < 32; i += 8)
        t[threadIdx.y + i][threadIdx.x] = in[(size_t)(by + threadIdx.y + i) * DMODEL + bx + threadIdx.x];
    __syncthreads();
    #pragma unroll
    for (int i = 0; i < 32; i += 8) {
        float v = t[threadIdx.x][threadIdx.y + i];
        oh[(size_t)(bx + threadIdx.y + i) * DMODEL + by + threadIdx.x] = __float2half(v);
    }
}

// ---------------------------------------------------------------------------
// Single-fp16 mma.sync GEMM: C[m,n] = sum_k A[m,k]*B[n,k].
// Tile 128x128, BK=64, warp 32x64, 3-stage cp.async, 128B-row swizzle, 2 CTA/SM.
// Stage = A(16K)|B(16K) = 32KB.
// EPI: 0=fp32 C; 1=three scaled fp16; 2=one scaled fp16; 4=plain fp16.
// ---------------------------------------------------------------------------
static constexpr int STAGE_B  = 32768;
static constexpr int SMEM_DYN = 3 * STAGE_B;     // 98304

template<int EPI>
__global__ __launch_bounds__(256, 2)
void gemm_fp16(const __half* __restrict__ Ah, const __half* __restrict__ Bh,
               float* __restrict__ C,
               const float* __restrict__ s0, const float* __restrict__ s1,
               const float* __restrict__ s2,
               __half* __restrict__ P0, __half* __restrict__ P1,
               __half* __restrict__ P2)
{
    extern __shared__ char smem[];
    const int tid  = threadIdx.x;
    const int lane = tid & 31;
    const int wid  = tid >> 5;
    const int bm   = blockIdx.y * 128;
    const int bn   = blockIdx.x * 128;
    const int wm0  = (wid & 3) * 32;
    const int wn0  = (wid >> 2) * 64;
    const uint32_t sbase = smem_u32(smem);

    // cp.async geometry: 128B rows, 8 chunks/row; thread covers 4 A + 4 B chunks
    const int arow = tid >> 1;                  // 0..127
    const int acol = (tid & 1) * 4;             // chunk base 0 or 4

    const char* gA = (const char*)Ah + (size_t)(bm + arow) * 2048 + acol * 16;
    const char* gB = (const char*)Bh + (size_t)(bn + arow) * 2048 + acol * 16;
    uint32_t soA[4];
    #pragma unroll
    for (int i = 0; i < 4; ++i)
        soA[i] = swz128((uint32_t)(arow * 128 + (acol + i) * 16));

    auto issue_stage = [&](int c, int s) {
        const size_t k0b = (size_t)c * 128;     // 64 k * 2B
        const uint32_t st = sbase + (uint32_t)s * STAGE_B;
        #pragma unroll
        for (int i = 0; i < 4; ++i)
            CPASYNC16(st + soA[i], gA + k0b + i * 16);
        #pragma unroll
        for (int i = 0; i < 4; ++i)
            CPASYNC16(st + 16384u + soA[i], gB + k0b + i * 16);
        CPCOMMIT();
    };

    float acc[2][8][4];
    #pragma unroll
    for (int i = 0; i < 2; ++i)
        #pragma unroll
        for (int j = 0; j < 8; ++j)
            #pragma unroll
            for (int q = 0; q < 4; ++q) acc[i][j][q] = 0.f;

    uint32_t aoff[2], boff[4];
    #pragma unroll
    for (int mt = 0; mt < 2; ++mt)
        aoff[mt] = (uint32_t)((wm0 + mt * 16 + (lane & 15)) * 128 + ((lane >> 4) << 4));
    #pragma unroll
    for (int bb = 0; bb < 4; ++bb)
        boff[bb] = (uint32_t)((wn0 + bb * 16 + (lane & 7) + ((lane >> 4) << 3)) * 128 + ((lane & 8) << 1));

    auto compute = [&](int s) {
        const uint32_t st = sbase + (uint32_t)s * STAGE_B;
        #pragma unroll
        for (int ks = 0; ks < 4; ++ks) {
            const uint32_t kb = ks * 32u;
            uint32_t af[2][4], bf[4][4];
            #pragma unroll
            for (int mt = 0; mt < 2; ++mt)
                LDMX4(af[mt][0], af[mt][1], af[mt][2], af[mt][3],
                      st + swz128(aoff[mt] + kb));
            #pragma unroll
            for (int bb = 0; bb < 4; ++bb)
                LDMX4(bf[bb][0], bf[bb][1], bf[bb][2], bf[bb][3],
                      st + 16384u + swz128(boff[bb] + kb));
            #pragma unroll
            for (int bb = 0; bb < 4; ++bb)
                #pragma unroll
                for (int mt = 0; mt < 2; ++mt) {
                    MMA16816_2(acc[mt][2 * bb],     af[mt], bf[bb][0], bf[bb][1]);
                    MMA16816_2(acc[mt][2 * bb + 1], af[mt], bf[bb][2], bf[bb][3]);
                }
        }
    };

    issue_stage(0, 0);
    issue_stage(1, 1);

    for (int c = 0; c < 16; ++c) {
        if (c < 15) { CPWAIT(1); } else { CPWAIT(0); }
        __syncthreads();
        if (c + 2 < 16) issue_stage(c + 2, (c + 2) % 3);
        compute(c % 3);
    }

    // ---- epilogue
    #pragma unroll
    for (int mt = 0; mt < 2; ++mt) {
        const int m = bm + wm0 + mt * 16 + (lane >> 2);
        #pragma unroll
        for (int nf = 0; nf < 8; ++nf) {
            const int n = bn + wn0 + nf * 8 + (lane & 3) * 2;
            const size_t o0 = (size_t)m * DMODEL + n;
            const size_t o1 = (size_t)(m + 8) * DMODEL + n;
            if (EPI == 0) {
                float2 v0 = {acc[mt][nf][0], acc[mt][nf][1]};
                float2 v1 = {acc[mt][nf][2], acc[mt][nf][3]};
                *reinterpret_cast<float2*>(C + o0) = v0;
                *reinterpret_cast<float2*>(C + o1) = v1;
            } else if (EPI == 4) {
                *reinterpret_cast<uint32_t*>(P0 + o0) = packh(acc[mt][nf][0], acc[mt][nf][1]);
                *reinterpret_cast<uint32_t*>(P0 + o1) = packh(acc[mt][nf][2], acc[mt][nf][3]);
            } else {
                float2 sc0 = *reinterpret_cast<const float2*>(s0 + n);
                *reinterpret_cast<uint32_t*>(P0 + o0) = packh(acc[mt][nf][0] * sc0.x, acc[mt][nf][1] * sc0.y);
                *reinterpret_cast<uint32_t*>(P0 + o1) = packh(acc[mt][nf][2] * sc0.x, acc[mt][nf][3] * sc0.y);
                if (EPI == 1) {
                    float2 sc1 = *reinterpret_cast<const float2*>(s1 + n);
                    float2 sc2 = *reinterpret_cast<const float2*>(s2 + n);
                    *reinterpret_cast<uint32_t*>(P1 + o0) = packh(acc[mt][nf][0] * sc1.x, acc[mt][nf][1] * sc1.y);
                    *reinterpret_cast<uint32_t*>(P1 + o1) = packh(acc[mt][nf][2] * sc1.x, acc[mt][nf][3] * sc1.y);
                    *reinterpret_cast<uint32_t*>(P2 + o0) = packh(acc[mt][nf][0] * sc2.x, acc[mt][nf][1] * sc2.y);
                    *reinterpret_cast<uint32_t*>(P2 + o1) = packh(acc[mt][nf][2] * sc2.x, acc[mt][nf][3] * sc2.y);
                }
            }
        }
    }
}

// ---------------------------------------------------------------------------
// fp16 flash attention: Q/K/V single fp16, P split (hi/lo, register-local).
// K/V via 3-stage cp.async; Q copied smem-direct once.
// smem (fp16 elems): Q[0..9216), stages at 9216 + s*9216 (K 64x72, V 64x72).
// ---------------------------------------------------------------------------
static constexpr int RSA    = 72;
static constexpr int QMAT_E = 128 * RSA;           // 9216
static constexpr int STG_E  = 2 * 64 * RSA;        // 9216
static constexpr int ASMEM  = (QMAT_E + 3 * STG_E) * 2;   // 73728 bytes

__global__ __launch_bounds__(256, 1)
void attn_mma(const __half* __restrict__ Qh,
              const __half* __restrict__ Kh, const __half* __restrict__ Vh,
              const float* __restrict__ bias,
              __half* __restrict__ AOh)
{
    extern __shared__ __half asmem[];
    const int tid  = threadIdx.x;
    const int lane = tid & 31;
    const int w    = tid >> 5;
    const int qt   = (int)gridDim.x - 1 - (int)blockIdx.x;   // heavy first
    const int h    = blockIdx.y;
    const int b    = blockIdx.z;
    const int q0   = qt * 128;
    const uint32_t sbase = smem_u32(asmem);
    const int nt   = 2 * qt + 2;

    const int krow = tid >> 2;
    const int kseg = (tid & 3) * 32;
    const char* gK = (const char*)(Kh + (size_t)(b * SEQ + krow) * DMODEL + h * DHEAD) + kseg;
    const char* gV = (const char*)(Vh + (size_t)(b * SEQ + krow) * DMODEL + h * DHEAD) + kseg;
    const uint32_t kvoff = (uint32_t)(krow * 144 + kseg);

    auto issue_kv = [&](int kt, int s) {
        const size_t gofs = (size_t)kt * 64 * 2048;
        const uint32_t st = sbase + (uint32_t)(QMAT_E + s * STG_E) * 2;
        CPASYNC16(st + kvoff,              gK + gofs);
        CPASYNC16(st + kvoff + 16,         gK + gofs + 16);
        CPASYNC16(st + 9216u + kvoff,      gV + gofs);
        CPASYNC16(st + 9216u + kvoff + 16, gV + gofs + 16);
        CPCOMMIT();
    };

    issue_kv(0, 0);
    issue_kv(1, 1);

    // ---- copy Q gmem->smem (16B chunks)
    {
        const __half* Qb = Qh + (size_t)(b * SEQ + q0) * DMODEL + h * DHEAD;
        #pragma unroll
        for (int i = 0; i < 4; ++i) {
            int idx = tid + i * 256;             // 0..1023
            int r   = idx >> 3;
            int c16 = idx & 7;
            uint4 v = *reinterpret_cast<const uint4*>(Qb + (size_t)r * DMODEL + c16 * 8);
            *reinterpret_cast<uint4*>(asmem + r * RSA + c16 * 8) = v;
        }
    }
    __syncthreads();

    uint32_t qf[4][4];
    #pragma unroll
    for (int ks = 0; ks < 4; ++ks) {
        const uint32_t off = ((w * 16 + (lane & 15)) * RSA + ks * 16 + ((lane >> 4) << 3)) * 2;
        LDMX4(qf[ks][0], qf[ks][1], qf[ks][2], qf[ks][3], sbase + off);
    }

    float m0 = -1e30f, m1 = -1e30f, l0 = 0.f, l1 = 0.f;
    float o[8][4];
    #pragma unroll
    for (int j = 0; j < 8; ++j)
        #pragma unroll
        for (int q = 0; q < 4; ++q) o[j][q] = 0.f;

    const int q_r0 = q0 + w * 16 + (lane >> 2);
    const int q_r1 = q_r0 + 8;
    const float* bph = bias + (size_t)h * SEQ * SEQ;

    for (int kt = 0; kt < nt; ++kt) {
        const int k0 = kt * 64;
        if (kt + 1 < nt) { CPWAIT(1); } else { CPWAIT(0); }
        __syncthreads();
        if (kt + 2 < nt) issue_kv(kt + 2, (kt + 2) % 3);

        const uint32_t Khu = sbase + (uint32_t)(QMAT_E + (kt % 3) * STG_E) * 2;
        const uint32_t Vhu = Khu + 9216u;

        // ---- S = Q K^T (single)
        float sacc[8][4];
        #pragma unroll
        for (int j = 0; j < 8; ++j)
            #pragma unroll
            for (int q = 0; q < 4; ++q) sacc[j][q] = 0.f;
        #pragma unroll
        for (int ks = 0; ks < 4; ++ks) {
            #pragma unroll
            for (int bb = 0; bb < 4; ++bb) {
                const uint32_t off =
                    ((bb * 16 + (lane & 7) + ((lane >> 4) << 3)) * RSA + ks * 16 + (lane & 8)) * 2;
                uint32_t b0, b1, b2, b3;
                LDMX4(b0, b1, b2, b3, Khu + off);
                MMA16816_2(sacc[2 * bb],     qf[ks], b0, b1);
                MMA16816_2(sacc[2 * bb + 1], qf[ks], b2, b3);
            }
        }

        // ---- scale + bias (log2 domain) + causal mask
        const bool mask = (kt >= 2 * qt);
        const float* r0p = bph + (size_t)q_r0 * SEQ + k0 + 2 * (lane & 3);
        const float* r1p = bph + (size_t)q_r1 * SEQ + k0 + 2 * (lane & 3);
        #pragma unroll
        for (int nf = 0; nf < 8; ++nf) {
            float2 b0 = *reinterpret_cast<const float2*>(r0p + nf * 8);
            float2 b1 = *reinterpret_cast<const float2*>(r1p + nf * 8);
            float v0 = fmaf(sacc[nf][0], 0.18033688f, b0.x * 1.4426950f);
            float v1 = fmaf(sacc[nf][1], 0.18033688f, b0.y * 1.4426950f);
            float v2 = fmaf(sacc[nf][2], 0.18033688f, b1.x * 1.4426950f);
            float v3 = fmaf(sacc[nf][3], 0.18033688f, b1.y * 1.4426950f);
            if (mask) {
                const int kc = k0 + nf * 8 + 2 * (lane & 3);
                if (kc     > q_r0) v0 = -1e30f;
                if (kc + 1 > q_r0) v1 = -1e30f;
                if (kc     > q_r1) v2 = -1e30f;
                if (kc + 1 > q_r1) v3 = -1e30f;
            }
            sacc[nf][0] = v0; sacc[nf][1] = v1; sacc[nf][2] = v2; sacc[nf][3] = v3;
        }

        // ---- online softmax (base 2)
        float m0n = m0, m1n = m1;
        #pragma unroll
        for (int nf = 0; nf < 8; ++nf) {
            m0n = fmaxf(m0n, fmaxf(sacc[nf][0], sacc[nf][1]));
            m1n = fmaxf(m1n, fmaxf(sacc[nf][2], sacc[nf][3]));
        }
        m0n = fmaxf(m0n, __shfl_xor_sync(0xffffffffu, m0n, 1));
        m0n = fmaxf(m0n, __shfl_xor_sync(0xffffffffu, m0n, 2));
        m1n = fmaxf(m1n, __shfl_xor_sync(0xffffffffu, m1n, 1));
        m1n = fmaxf(m1n, __shfl_xor_sync(0xffffffffu, m1n, 2));
        const float c0 = exp2p(m0 - m0n), c1 = exp2p(m1 - m1n);
        m0 = m0n; m1 = m1n;
        l0 *= c0;  l1 *= c1;
        #pragma unroll
        for (int nf = 0; nf < 8; ++nf) {
            o[nf][0] *= c0; o[nf][1] *= c0;
            o[nf][2] *= c1; o[nf][3] *= c1;
        }

        uint32_t pA0[8], pA1[8], pL0[8], pL1[8];
        #pragma unroll
        for (int nf = 0; nf < 8; ++nf) {
            float p0 = exp2p(sacc[nf][0] - m0);
            float p1 = exp2p(sacc[nf][1] - m0);
            float p2 = exp2p(sacc[nf][2] - m1);
            float p3 = exp2p(sacc[nf][3] - m1);
            l0 += p0 + p1; l1 += p2 + p3;
            __half h0 = __float2half(p0), h1 = __float2half(p1);
            __half h2 = __float2half(p2), h3 = __float2half(p3);
            pA0[nf] = (uint32_t)__half_as_ushort(h0) | ((uint32_t)__half_as_ushort(h1) << 16);
            pA1[nf] = (uint32_t)__half_as_ushort(h2) | ((uint32_t)__half_as_ushort(h3) << 16);
            pL0[nf] = packh(p0 - __half2float(h0), p1 - __half2float(h1));
            pL1[nf] = packh(p2 - __half2float(h2), p3 - __half2float(h3));
        }

        // ---- O += P V (P split, V single via ldmatrix.trans)
        #pragma unroll
        for (int ks = 0; ks < 4; ++ks) {
            uint32_t ah[4] = { pA0[2 * ks], pA1[2 * ks], pA0[2 * ks + 1], pA1[2 * ks + 1] };
            uint32_t al[4] = { pL0[2 * ks], pL1[2 * ks], pL0[2 * ks + 1], pL1[2 * ks + 1] };
            #pragma unroll
            for (int ng = 0; ng < 4; ++ng) {
                const uint32_t off =
                    ((ks * 16 + (lane & 7) + (lane & 8)) * RSA + ng * 16 + ((lane >> 4) << 3)) * 2;
                uint32_t h0, h1, h2, h3;
                LDMX4T(h0, h1, h2, h3, Vhu + off);
                MMA16816_2(o[2 * ng],     ah, h0, h1);
                MMA16816_2(o[2 * ng],     al, h0, h1);
                MMA16816_2(o[2 * ng + 1], ah, h2, h3);
                MMA16816_2(o[2 * ng + 1], al, h2, h3);
            }
        }
    }

    l0 += __shfl_xor_sync(0xffffffffu, l0, 1);
    l0 += __shfl_xor_sync(0xffffffffu, l0, 2);
    l1 += __shfl_xor_sync(0xffffffffu, l1, 1);
    l1 += __shfl_xor_sync(0xffffffffu, l1, 2);
    const float i0 = 1.f / l0, i1 = 1.f / l1;
    const size_t r0off = (size_t)(b * SEQ + q_r0) * DMODEL + h * DHEAD + 2 * (lane & 3);
    const size_t r1off = (size_t)(b * SEQ + q_r1) * DMODEL + h * DHEAD + 2 * (lane & 3);
    #pragma unroll
    for (int nf = 0; nf < 8; ++nf) {
        *reinterpret_cast<uint32_t*>(AOh + r0off + nf * 8) = packh(o[nf][0] * i0, o[nf][1] * i0);
        *reinterpret_cast<uint32_t*>(AOh + r1off + nf * 8) = packh(o[nf][2] * i1, o[nf][3] * i1);
    }
}

// ---------------------------------------------------------------------------
extern "C" void kernel_launch(void* const* d_in, const int* in_sizes, int n_in,
                              void* d_out, int out_size)
{
    const float* x     = (const float*)d_in[0];
    const float* basis = (const float*)d_in[1];
    const float* sq    = (const float*)d_in[2];
    const float* sk    = (const float*)d_in[3];
    const float* sv    = (const float*)d_in[4];
    const float* so    = (const float*)d_in[5];
    const float* bias  = (const float*)d_in[6];
    float*       out   = (float*)d_out;

    __half *Xh, *BTh, *Bmh, *XBq, *XBk, *XBv, *AOh, *O1h, *Qh, *Kh, *Vh;
    cudaGetSymbolAddress((void**)&Xh,  g_Xh);
    cudaGetSymbolAddress((void**)&BTh, g_BTh);
    cudaGetSymbolAddress((void**)&Bmh, g_Bmh);
    cudaGetSymbolAddress((void**)&XBq, g_XBq);
    cudaGetSymbolAddress((void**)&XBk, g_XBk);
    cudaGetSymbolAddress((void**)&XBv, g_XBv);
    cudaGetSymbolAddress((void**)&AOh, g_AOh);
    cudaGetSymbolAddress((void**)&O1h, g_O1h);
    cudaGetSymbolAddress((void**)&Qh, g_Qh);
    cudaGetSymbolAddress((void**)&Kh, g_Kh);
    cudaGetSymbolAddress((void**)&Vh, g_Vh);

    cudaFuncSetAttribute(gemm_fp16<0>, cudaFuncAttributeMaxDynamicSharedMemorySize, SMEM_DYN);
    cudaFuncSetAttribute(gemm_fp16<1>, cudaFuncAttributeMaxDynamicSharedMemorySize, SMEM_DYN);
    cudaFuncSetAttribute(gemm_fp16<2>, cudaFuncAttributeMaxDynamicSharedMemorySize, SMEM_DYN);
    cudaFuncSetAttribute(gemm_fp16<4>, cudaFuncAttributeMaxDynamicSharedMemorySize, SMEM_DYN);
    cudaFuncSetAttribute(attn_mma, cudaFuncAttributeMaxDynamicSharedMemorySize, ASMEM);

    // pre-truncate inputs
    trunc_plain<<<MROWS * DMODEL / 1024, 256>>>((const float4*)x, Xh);
    trunc_plain<<<DMODEL * DMODEL / 1024, 256>>>((const float4*)basis, Bmh);
    trans_trunc<<<dim3(32, 32), dim3(32, 8)>>>(basis, BTh);

    const dim3 gg(DMODEL / 128, MROWS / 128);
    // G1: XB = X @ basis, emits scale-fused singles for q/k/v
    gemm_fp16<1><<<gg, 256, SMEM_DYN>>>(Xh, BTh, nullptr, sq, sk, sv, XBq, XBk, XBv);
    // G2-4: Q/K/V fp16 single
    gemm_fp16<4><<<gg, 256, SMEM_DYN>>>(XBq, Bmh, nullptr, nullptr, nullptr, nullptr,
                                        Qh, nullptr, nullptr);
    gemm_fp16<4><<<gg, 256, SMEM_DYN>>>(XBk, Bmh, nullptr, nullptr, nullptr, nullptr,
                                        Kh, nullptr, nullptr);
    gemm_fp16<4><<<gg, 256, SMEM_DYN>>>(XBv, Bmh, nullptr, nullptr, nullptr, nullptr,
                                        Vh, nullptr, nullptr);

    attn_mma<<<dim3(SEQ / 128, NHEADS, BATCH), 256, ASMEM>>>(Qh, Kh, Vh, bias, AOh);

    // G5: O1 = AO @ basis, so-fused single
    gemm_fp16<2><<<gg, 256, SMEM_DYN>>>(AOh, BTh, nullptr, so, nullptr, nullptr,
                                        O1h, nullptr, nullptr);
    // G6: out = O1s @ basis^T, fp32
    gemm_fp16<0><<<gg, 256, SMEM_DYN>>>(O1h, Bmh, out, nullptr, nullptr, nullptr,
                                        nullptr, nullptr, nullptr);
}

// round 11
// speedup vs baseline: 1.8241x; 1.1207x over previous
#include <cuda_runtime.h>
#include <cuda_fp16.h>
#include <cstdint>
#include <cstddef>

#define SEQ    2048
#define BATCH  2
#define DMODEL 1024
#define NHEADS 16
#define DHEAD  64
#define MROWS  (BATCH*SEQ)

// ---------------- scratch (device globals; allocation-free rule) ------------
__device__ __half g_Xh [(size_t)MROWS*DMODEL];
__device__ __half g_BTh[(size_t)DMODEL*DMODEL];            // basis^T, fp16
__device__ __half g_Bmh[(size_t)DMODEL*DMODEL];            // basis, fp16
__device__ __half g_XB3[(size_t)3*MROWS*DMODEL];           // XBq | XBk | XBv
__device__ __half g_QKV[(size_t)3*MROWS*DMODEL];           // Q | K | V
__device__ __half g_AOh[(size_t)MROWS*DMODEL];
__device__ __half g_O1h[(size_t)MROWS*DMODEL];

// ---------------------------------------------------------------------------
__device__ __forceinline__ uint32_t smem_u32(const void* p) {
    uint32_t a;
    asm("{ .reg .u64 t; cvta.to.shared.u64 t, %1; cvt.u32.u64 %0, t; }"
        : "=r"(a) : "l"(p));
    return a;
}

#define LDMX4(r0, r1, r2, r3, addr) \
    asm volatile("ldmatrix.sync.aligned.m8n8.x4.shared.b16 {%0,%1,%2,%3}, [%4];" \
                 : "=r"(r0), "=r"(r1), "=r"(r2), "=r"(r3) : "r"(addr))

#define LDMX4T(r0, r1, r2, r3, addr) \
    asm volatile("ldmatrix.sync.aligned.m8n8.x4.trans.shared.b16 {%0,%1,%2,%3}, [%4];" \
                 : "=r"(r0), "=r"(r1), "=r"(r2), "=r"(r3) : "r"(addr))

#define MMA16816_2(d, a, b0r, b1r) \
    asm volatile("mma.sync.aligned.m16n8k16.row.col.f32.f16.f16.f32 " \
                 "{%0,%1,%2,%3}, {%4,%5,%6,%7}, {%8,%9}, {%0,%1,%2,%3};" \
                 : "+f"((d)[0]), "+f"((d)[1]), "+f"((d)[2]), "+f"((d)[3]) \
                 : "r"((a)[0]), "r"((a)[1]), "r"((a)[2]), "r"((a)[3]), \
                   "r"(b0r), "r"(b1r))

#define CPASYNC16(dst, src) \
    asm volatile("cp.async.cg.shared.global [%0], [%1], 16;" \
                 :: "r"(dst), "l"(src))
#define CPCOMMIT()  asm volatile("cp.async.commit_group;" ::: "memory")
#define CPWAIT(n)   asm volatile("cp.async.wait_group %0;" :: "n"(n) : "memory")

// XOR swizzle for 128B rows: chunk(0..7) ^= row&7 -> conflict-free ldmatrix
__device__ __forceinline__ uint32_t swz128(uint32_t o) {
    return o ^ (((o >> 7) & 7u) << 4);
}

__device__ __forceinline__ uint32_t packh(float a, float b) {
    __half x = __float2half(a), y = __float2half(b);
    return (uint32_t)__half_as_ushort(x) | ((uint32_t)__half_as_ushort(y) << 16);
}

__device__ __forceinline__ void trunc_store(void* hp, float4 v) {
    uint2 hu;
    hu.x = packh(v.x, v.y);
    hu.y = packh(v.z, v.w);
    *reinterpret_cast<uint2*>(hp) = hu;
}

// 2^y via FMA-pipe polynomial (no MUFU)
__device__ __forceinline__ float exp2p(float y) {
    y = fmaxf(y, -120.f);
    float t = y + 12582912.f;
    int   n = (__float_as_int(t) & 0x7FFFFF) - 0x400000;
    float f = y - (t - 12582912.f);
    float p = 1.3333558146e-3f;
    p = fmaf(p, f, 9.6181291076e-3f);
    p = fmaf(p, f, 5.5504108664e-2f);
    p = fmaf(p, f, 2.4022650695e-1f);
    p = fmaf(p, f, 6.9314718056e-1f);
    p = fmaf(p, f, 1.0f);
    return __int_as_float(__float_as_int(p) + (n << 23));
}

// ---------------------------------------------------------------------------
// Pre-truncate helpers
// ---------------------------------------------------------------------------
__global__ void trunc_plain(const float4* __restrict__ in, __half* __restrict__ h) {
    size_t i = (size_t)blockIdx.x * 256 + threadIdx.x;
    trunc_store(h + 4 * i, in[i]);
}

__global__ void trans_trunc(const float* __restrict__ in, __half* __restrict__ oh) {
    __shared__ float t[32][33];
    int bx = blockIdx.x * 32, by = blockIdx.y * 32;
    #pragma unroll
    for (int i = 0; i < 32; i += 8)
        t[threadIdx.y + i][threadIdx.x] = in[(size_t)(by + threadIdx.y + i) * DMODEL + bx + threadIdx.x];
    __syncthreads();
    #pragma unroll
    for (int i = 0; i < 32; i += 8) {
        float v = t[threadIdx.x][threadIdx.y + i];
        oh[(size_t)(bx + threadIdx.y + i) * DMODEL + by + threadIdx.x] = __float2half(v);
    }
}

// ---------------------------------------------------------------------------
// Single-fp16 mma.sync GEMM: C[m,n] = sum_k A[m,k]*B[n,k].
// Tile 128x128, BK=64, warp 32x64, 3-stage cp.async, 128B-row swizzle, 2 CTA/SM.
// EPI: 0=fp32 C; 1=three scaled fp16; 2=one scaled fp16; 4=plain fp16.
// ---------------------------------------------------------------------------
static constexpr int STAGE_B  = 32768;
static constexpr int SMEM_DYN = 3 * STAGE_B;     // 98304

template<int EPI>
__global__ __launch_bounds__(256, 2)
void gemm_fp16(const __half* __restrict__ Ah, const __half* __restrict__ Bh,
               float* __restrict__ C,
               const float* __restrict__ s0, const float* __restrict__ s1,
               const float* __restrict__ s2,
               __half* __restrict__ P0, __half* __restrict__ P1,
               __half* __restrict__ P2)
{
    extern __shared__ char smem[];
    const int tid  = threadIdx.x;
    const int lane = tid & 31;
    const int wid  = tid >> 5;
    const int bm   = blockIdx.y * 128;
    const int bn   = blockIdx.x * 128;
    const int wm0  = (wid & 3) * 32;
    const int wn0  = (wid >> 2) * 64;
    const uint32_t sbase = smem_u32(smem);

    const int arow = tid >> 1;                  // 0..127
    const int acol = (tid & 1) * 4;             // chunk base 0 or 4

    const char* gA = (const char*)Ah + (size_t)(bm + arow) * 2048 + acol * 16;
    const char* gB = (const char*)Bh + (size_t)(bn + arow) * 2048 + acol * 16;
    uint32_t soA[4];
    #pragma unroll
    for (int i = 0; i < 4; ++i)
        soA[i] = swz128((uint32_t)(arow * 128 + (acol + i) * 16));

    auto issue_stage = [&](int c, int s) {
        const size_t k0b = (size_t)c * 128;
        const uint32_t st = sbase + (uint32_t)s * STAGE_B;
        #pragma unroll
        for (int i = 0; i < 4; ++i)
            CPASYNC16(st + soA[i], gA + k0b + i * 16);
        #pragma unroll
        for (int i = 0; i < 4; ++i)
            CPASYNC16(st + 16384u + soA[i], gB + k0b + i * 16);
        CPCOMMIT();
    };

    float acc[2][8][4];
    #pragma unroll
    for (int i = 0; i < 2; ++i)
        #pragma unroll
        for (int j = 0; j < 8; ++j)
            #pragma unroll
            for (int q = 0; q < 4; ++q) acc[i][j][q] = 0.f;

    uint32_t aoff[2], boff[4];
    #pragma unroll
    for (int mt = 0; mt < 2; ++mt)
        aoff[mt] = (uint32_t)((wm0 + mt * 16 + (lane & 15)) * 128 + ((lane >> 4) << 4));
    #pragma unroll
    for (int bb = 0; bb < 4; ++bb)
        boff[bb] = (uint32_t)((wn0 + bb * 16 + (lane & 7) + ((lane >> 4) << 3)) * 128 + ((lane & 8) << 1));

    auto compute = [&](int s) {
        const uint32_t st = sbase + (uint32_t)s * STAGE_B;
        #pragma unroll
        for (int ks = 0; ks < 4; ++ks) {
            const uint32_t kb = ks * 32u;
            uint32_t af[2][4], bf[4][4];
            #pragma unroll
            for (int mt = 0; mt < 2; ++mt)
                LDMX4(af[mt][0], af[mt][1], af[mt][2], af[mt][3],
                      st + swz128(aoff[mt] + kb));
            #pragma unroll
            for (int bb = 0; bb < 4; ++bb)
                LDMX4(bf[bb][0], bf[bb][1], bf[bb][2], bf[bb][3],
                      st + 16384u + swz128(boff[bb] + kb));
            #pragma unroll
            for (int bb = 0; bb < 4; ++bb)
                #pragma unroll
                for (int mt = 0; mt < 2; ++mt) {
                    MMA16816_2(acc[mt][2 * bb],     af[mt], bf[bb][0], bf[bb][1]);
                    MMA16816_2(acc[mt][2 * bb + 1], af[mt], bf[bb][2], bf[bb][3]);
                }
        }
    };

    issue_stage(0, 0);
    issue_stage(1, 1);

    for (int c = 0; c < 16; ++c) {
        if (c < 15) { CPWAIT(1); } else { CPWAIT(0); }
        __syncthreads();
        if (c + 2 < 16) issue_stage(c + 2, (c + 2) % 3);
        compute(c % 3);
    }

    // ---- epilogue
    #pragma unroll
    for (int mt = 0; mt < 2; ++mt) {
        const int m = bm + wm0 + mt * 16 + (lane >> 2);
        #pragma unroll
        for (int nf = 0; nf < 8; ++nf) {
            const int n = bn + wn0 + nf * 8 + (lane & 3) * 2;
            const size_t o0 = (size_t)m * DMODEL + n;
            const size_t o1 = (size_t)(m + 8) * DMODEL + n;
            if (EPI == 0) {
                float2 v0 = {acc[mt][nf][0], acc[mt][nf][1]};
                float2 v1 = {acc[mt][nf][2], acc[mt][nf][3]};
                *reinterpret_cast<float2*>(C + o0) = v0;
                *reinterpret_cast<float2*>(C + o1) = v1;
            } else if (EPI == 4) {
                *reinterpret_cast<uint32_t*>(P0 + o0) = packh(acc[mt][nf][0], acc[mt][nf][1]);
                *reinterpret_cast<uint32_t*>(P0 + o1) = packh(acc[mt][nf][2], acc[mt][nf][3]);
            } else {
                float2 sc0 = *reinterpret_cast<const float2*>(s0 + n);
                *reinterpret_cast<uint32_t*>(P0 + o0) = packh(acc[mt][nf][0] * sc0.x, acc[mt][nf][1] * sc0.y);
                *reinterpret_cast<uint32_t*>(P0 + o1) = packh(acc[mt][nf][2] * sc0.x, acc[mt][nf][3] * sc0.y);
                if (EPI == 1) {
                    float2 sc1 = *reinterpret_cast<const float2*>(s1 + n);
                    float2 sc2 = *reinterpret_cast<const float2*>(s2 + n);
                    *reinterpret_cast<uint32_t*>(P1 + o0) = packh(acc[mt][nf][0] * sc1.x, acc[mt][nf][1] * sc1.y);
                    *reinterpret_cast<uint32_t*>(P1 + o1) = packh(acc[mt][nf][2] * sc1.x, acc[mt][nf][3] * sc1.y);
                    *reinterpret_cast<uint32_t*>(P2 + o0) = packh(acc[mt][nf][0] * sc2.x, acc[mt][nf][1] * sc2.y);
                    *reinterpret_cast<uint32_t*>(P2 + o1) = packh(acc[mt][nf][2] * sc2.x, acc[mt][nf][3] * sc2.y);
                }
            }
        }
    }
}

// ---------------------------------------------------------------------------
// fp16 flash attention: Q/K/V/P all single fp16; bias loads hoisted above MMA.
// K/V via 3-stage cp.async; Q copied smem-direct once.
// ---------------------------------------------------------------------------
static constexpr int RSA    = 72;
static constexpr int QMAT_E = 128 * RSA;           // 9216
static constexpr int STG_E  = 2 * 64 * RSA;        // 9216
static constexpr int ASMEM  = (QMAT_E + 3 * STG_E) * 2;   // 73728 bytes

__global__ __launch_bounds__(256, 1)
void attn_mma(const __half* __restrict__ Qh,
              const __half* __restrict__ Kh, const __half* __restrict__ Vh,
              const float* __restrict__ bias,
              __half* __restrict__ AOh)
{
    extern __shared__ __half asmem[];
    const int tid  = threadIdx.x;
    const int lane = tid & 31;
    const int w    = tid >> 5;
    const int qt   = (int)gridDim.x - 1 - (int)blockIdx.x;   // heavy first
    const int h    = blockIdx.y;
    const int b    = blockIdx.z;
    const int q0   = qt * 128;
    const uint32_t sbase = smem_u32(asmem);
    const int nt   = 2 * qt + 2;

    const int krow = tid >> 2;
    const int kseg = (tid & 3) * 32;
    const char* gK = (const char*)(Kh + (size_t)(b * SEQ + krow) * DMODEL + h * DHEAD) + kseg;
    const char* gV = (const char*)(Vh + (size_t)(b * SEQ + krow) * DMODEL + h * DHEAD) + kseg;
    const uint32_t kvoff = (uint32_t)(krow * 144 + kseg);

    auto issue_kv = [&](int kt, int s) {
        const size_t gofs = (size_t)kt * 64 * 2048;
        const uint32_t st = sbase + (uint32_t)(QMAT_E + s * STG_E) * 2;
        CPASYNC16(st + kvoff,              gK + gofs);
        CPASYNC16(st + kvoff + 16,         gK + gofs + 16);
        CPASYNC16(st + 9216u + kvoff,      gV + gofs);
        CPASYNC16(st + 9216u + kvoff + 16, gV + gofs + 16);
        CPCOMMIT();
    };

    issue_kv(0, 0);
    issue_kv(1, 1);

    // ---- copy Q gmem->smem (16B chunks)
    {
        const __half* Qb = Qh + (size_t)(b * SEQ + q0) * DMODEL + h * DHEAD;
        #pragma unroll
        for (int i = 0; i < 4; ++i) {
            int idx = tid + i * 256;             // 0..1023
            int r   = idx >> 3;
            int c16 = idx & 7;
            uint4 v = *reinterpret_cast<const uint4*>(Qb + (size_t)r * DMODEL + c16 * 8);
            *reinterpret_cast<uint4*>(asmem + r * RSA + c16 * 8) = v;
        }
    }
    __syncthreads();

    uint32_t qf[4][4];
    #pragma unroll
    for (int ks = 0; ks < 4; ++ks) {
        const uint32_t off = ((w * 16 + (lane & 15)) * RSA + ks * 16 + ((lane >> 4) << 3)) * 2;
        LDMX4(qf[ks][0], qf[ks][1], qf[ks][2], qf[ks][3], sbase + off);
    }

    float m0 = -1e30f, m1 = -1e30f, l0 = 0.f, l1 = 0.f;
    float o[8][4];
    #pragma unroll
    for (int j = 0; j < 8; ++j)
        #pragma unroll
        for (int q = 0; q < 4; ++q) o[j][q] = 0.f;

    const int q_r0 = q0 + w * 16 + (lane >> 2);
    const int q_r1 = q_r0 + 8;
    const float* bph = bias + (size_t)h * SEQ * SEQ;

    for (int kt = 0; kt < nt; ++kt) {
        const int k0 = kt * 64;
        if (kt + 1 < nt) { CPWAIT(1); } else { CPWAIT(0); }
        __syncthreads();
        if (kt + 2 < nt) issue_kv(kt + 2, (kt + 2) % 3);

        const uint32_t Khu = sbase + (uint32_t)(QMAT_E + (kt % 3) * STG_E) * 2;
        const uint32_t Vhu = Khu + 9216u;

        // ---- hoisted bias loads (latency hides under the QK^T MMAs below)
        const float* r0p = bph + (size_t)q_r0 * SEQ + k0 + 2 * (lane & 3);
        const float* r1p = bph + (size_t)q_r1 * SEQ + k0 + 2 * (lane & 3);
        float2 bb0[8], bb1[8];
        #pragma unroll
        for (int nf = 0; nf < 8; ++nf) {
            bb0[nf] = *reinterpret_cast<const float2*>(r0p + nf * 8);
            bb1[nf] = *reinterpret_cast<const float2*>(r1p + nf * 8);
        }

        // ---- S = Q K^T (single)
        float sacc[8][4];
        #pragma unroll
        for (int j = 0; j < 8; ++j)
            #pragma unroll
            for (int q = 0; q < 4; ++q) sacc[j][q] = 0.f;
        #pragma unroll
        for (int ks = 0; ks < 4; ++ks) {
            #pragma unroll
            for (int bb = 0; bb < 4; ++bb) {
                const uint32_t off =
                    ((bb * 16 + (lane & 7) + ((lane >> 4) << 3)) * RSA + ks * 16 + (lane & 8)) * 2;
                uint32_t b0, b1, b2, b3;
                LDMX4(b0, b1, b2, b3, Khu + off);
                MMA16816_2(sacc[2 * bb],     qf[ks], b0, b1);
                MMA16816_2(sacc[2 * bb + 1], qf[ks], b2, b3);
            }
        }

        // ---- scale + bias (log2 domain) + causal mask
        const bool mask = (kt >= 2 * qt);
        #pragma unroll
        for (int nf = 0; nf < 8; ++nf) {
            float v0 = fmaf(sacc[nf][0], 0.18033688f, bb0[nf].x * 1.4426950f);
            float v1 = fmaf(sacc[nf][1], 0.18033688f, bb0[nf].y * 1.4426950f);
            float v2 = fmaf(sacc[nf][2], 0.18033688f, bb1[nf].x * 1.4426950f);
            float v3 = fmaf(sacc[nf][3], 0.18033688f, bb1[nf].y * 1.4426950f);
            if (mask) {
                const int kc = k0 + nf * 8 + 2 * (lane & 3);
                if (kc     > q_r0) v0 = -1e30f;
                if (kc + 1 > q_r0) v1 = -1e30f;
                if (kc     > q_r1) v2 = -1e30f;
                if (kc + 1 > q_r1) v3 = -1e30f;
            }
            sacc[nf][0] = v0; sacc[nf][1] = v1; sacc[nf][2] = v2; sacc[nf][3] = v3;
        }

        // ---- online softmax (base 2)
        float m0n = m0, m1n = m1;
        #pragma unroll
        for (int nf = 0; nf < 8; ++nf) {
            m0n = fmaxf(m0n, fmaxf(sacc[nf][0], sacc[nf][1]));
            m1n = fmaxf(m1n, fmaxf(sacc[nf][2], sacc[nf][3]));
        }
        m0n = fmaxf(m0n, __shfl_xor_sync(0xffffffffu, m0n, 1));
        m0n = fmaxf(m0n, __shfl_xor_sync(0xffffffffu, m0n, 2));
        m1n = fmaxf(m1n, __shfl_xor_sync(0xffffffffu, m1n, 1));
        m1n = fmaxf(m1n, __shfl_xor_sync(0xffffffffu, m1n, 2));
        const float c0 = exp2p(m0 - m0n), c1 = exp2p(m1 - m1n);
        m0 = m0n; m1 = m1n;
        l0 *= c0;  l1 *= c1;
        #pragma unroll
        for (int nf = 0; nf < 8; ++nf) {
            o[nf][0] *= c0; o[nf][1] *= c0;
            o[nf][2] *= c1; o[nf][3] *= c1;
        }

        uint32_t pA0[8], pA1[8];
        #pragma unroll
        for (int nf = 0; nf < 8; ++nf) {
            float p0 = exp2p(sacc[nf][0] - m0);
            float p1 = exp2p(sacc[nf][1] - m0);
            float p2 = exp2p(sacc[nf][2] - m1);
            float p3 = exp2p(sacc[nf][3] - m1);
            l0 += p0 + p1; l1 += p2 + p3;
            pA0[nf] = packh(p0, p1);
            pA1[nf] = packh(p2, p3);
        }

        // ---- O += P V (single, V via ldmatrix.trans)
        #pragma unroll
        for (int ks = 0; ks < 4; ++ks) {
            uint32_t ah[4] = { pA0[2 * ks], pA1[2 * ks], pA0[2 * ks + 1], pA1[2 * ks + 1] };
            #pragma unroll
            for (int ng = 0; ng < 4; ++ng) {
                const uint32_t off =
                    ((ks * 16 + (lane & 7) + (lane & 8)) * RSA + ng * 16 + ((lane >> 4) << 3)) * 2;
                uint32_t h0, h1, h2, h3;
                LDMX4T(h0, h1, h2, h3, Vhu + off);
                MMA16816_2(o[2 * ng],     ah, h0, h1);
                MMA16816_2(o[2 * ng + 1], ah, h2, h3);
            }
        }
    }

    l0 += __shfl_xor_sync(0xffffffffu, l0, 1);
    l0 += __shfl_xor_sync(0xffffffffu, l0, 2);
    l1 += __shfl_xor_sync(0xffffffffu, l1, 1);
    l1 += __shfl_xor_sync(0xffffffffu, l1, 2);
    const float i0 = 1.f / l0, i1 = 1.f / l1;
    const size_t r0off = (size_t)(b * SEQ + q_r0) * DMODEL + h * DHEAD + 2 * (lane & 3);
    const size_t r1off = (size_t)(b * SEQ + q_r1) * DMODEL + h * DHEAD + 2 * (lane & 3);
    #pragma unroll
    for (int nf = 0; nf < 8; ++nf) {
        *reinterpret_cast<uint32_t*>(AOh + r0off + nf * 8) = packh(o[nf][0] * i0, o[nf][1] * i0);
        *reinterpret_cast<uint32_t*>(AOh + r1off + nf * 8) = packh(o[nf][2] * i1, o[nf][3] * i1);
    }
}

// ---------------------------------------------------------------------------
extern "C" void kernel_launch(void* const* d_in, const int* in_sizes, int n_in,
                              void* d_out, int out_size)
{
    const float* x     = (const float*)d_in[0];
    const float* basis = (const float*)d_in[1];
    const float* sq    = (const float*)d_in[2];
    const float* sk    = (const float*)d_in[3];
    const float* sv    = (const float*)d_in[4];
    const float* so    = (const float*)d_in[5];
    const float* bias  = (const float*)d_in[6];
    float*       out   = (float*)d_out;

    __half *Xh, *BTh, *Bmh, *XB3, *QKV, *AOh, *O1h;
    cudaGetSymbolAddress((void**)&Xh,  g_Xh);
    cudaGetSymbolAddress((void**)&BTh, g_BTh);
    cudaGetSymbolAddress((void**)&Bmh, g_Bmh);
    cudaGetSymbolAddress((void**)&XB3, g_XB3);
    cudaGetSymbolAddress((void**)&QKV, g_QKV);
    cudaGetSymbolAddress((void**)&AOh, g_AOh);
    cudaGetSymbolAddress((void**)&O1h, g_O1h);

    const size_t SEG = (size_t)MROWS * DMODEL;
    __half* XBq = XB3;            __half* XBk = XB3 + SEG;  __half* XBv = XB3 + 2 * SEG;
    __half* Qh  = QKV;            __half* Kh  = QKV + SEG;  __half* Vh  = QKV + 2 * SEG;

    cudaFuncSetAttribute(gemm_fp16<0>, cudaFuncAttributeMaxDynamicSharedMemorySize, SMEM_DYN);
    cudaFuncSetAttribute(gemm_fp16<1>, cudaFuncAttributeMaxDynamicSharedMemorySize, SMEM_DYN);
    cudaFuncSetAttribute(gemm_fp16<2>, cudaFuncAttributeMaxDynamicSharedMemorySize, SMEM_DYN);
    cudaFuncSetAttribute(gemm_fp16<4>, cudaFuncAttributeMaxDynamicSharedMemorySize, SMEM_DYN);
    cudaFuncSetAttribute(attn_mma, cudaFuncAttributeMaxDynamicSharedMemorySize, ASMEM);

    // pre-truncate inputs
    trunc_plain<<<MROWS * DMODEL / 1024, 256>>>((const float4*)x, Xh);
    trunc_plain<<<DMODEL * DMODEL / 1024, 256>>>((const float4*)basis, Bmh);
    trans_trunc<<<dim3(32, 32), dim3(32, 8)>>>(basis, BTh);

    const dim3 gg(DMODEL / 128, MROWS / 128);
    // G1: XB = X @ basis, emits scale-fused singles for q/k/v
    gemm_fp16<1><<<gg, 256, SMEM_DYN>>>(Xh, BTh, nullptr, sq, sk, sv, XBq, XBk, XBv);
    // G2-4 merged: QKV = XB3 @ basis (batched along M: 12288 rows)
    const dim3 gqkv(DMODEL / 128, 3 * MROWS / 128);
    gemm_fp16<4><<<gqkv, 256, SMEM_DYN>>>(XB3, Bmh, nullptr, nullptr, nullptr, nullptr,
                                          QKV, nullptr, nullptr);

    attn_mma<<<dim3(SEQ / 128, NHEADS, BATCH), 256, ASMEM>>>(Qh, Kh, Vh, bias, AOh);

    // G5: O1 = AO @ basis, so-fused single
    gemm_fp16<2><<<gg, 256, SMEM_DYN>>>(AOh, BTh, nullptr, so, nullptr, nullptr,
                                        O1h, nullptr, nullptr);
    // G6: out = O1s @ basis^T, fp32
    gemm_fp16<0><<<gg, 256, SMEM_DYN>>>(O1h, Bmh, out, nullptr, nullptr, nullptr,
                                        nullptr, nullptr, nullptr);
}

// round 12
// speedup vs baseline: 1.9349x; 1.0607x over previous
#include <cuda_runtime.h>
#include <cuda_fp16.h>
#include <cstdint>
#include <cstddef>

#define SEQ    2048
#define BATCH  2
#define DMODEL 1024
#define NHEADS 16
#define DHEAD  64
#define MROWS  (BATCH*SEQ)

// ---------------- scratch (device globals; allocation-free rule) ------------
__device__ __half g_Xh [(size_t)MROWS*DMODEL];
__device__ __half g_BTh[(size_t)DMODEL*DMODEL];            // basis^T, fp16
__device__ __half g_Bmh[(size_t)DMODEL*DMODEL];            // basis, fp16
__device__ __half g_XB3[(size_t)3*MROWS*DMODEL];           // XBq | XBk | XBv
__device__ __half g_QKV[(size_t)3*MROWS*DMODEL];           // Q | K | V
__device__ __half g_AOh[(size_t)MROWS*DMODEL];
__device__ __half g_O1h[(size_t)MROWS*DMODEL];

// ---------------------------------------------------------------------------
__device__ __forceinline__ uint32_t smem_u32(const void* p) {
    uint32_t a;
    asm("{ .reg .u64 t; cvta.to.shared.u64 t, %1; cvt.u32.u64 %0, t; }"
        : "=r"(a) : "l"(p));
    return a;
}

#define LDMX4(r0, r1, r2, r3, addr) \
    asm volatile("ldmatrix.sync.aligned.m8n8.x4.shared.b16 {%0,%1,%2,%3}, [%4];" \
                 : "=r"(r0), "=r"(r1), "=r"(r2), "=r"(r3) : "r"(addr))

#define LDMX4T(r0, r1, r2, r3, addr) \
    asm volatile("ldmatrix.sync.aligned.m8n8.x4.trans.shared.b16 {%0,%1,%2,%3}, [%4];" \
                 : "=r"(r0), "=r"(r1), "=r"(r2), "=r"(r3) : "r"(addr))

#define MMA16816_2(d, a, b0r, b1r) \
    asm volatile("mma.sync.aligned.m16n8k16.row.col.f32.f16.f16.f32 " \
                 "{%0,%1,%2,%3}, {%4,%5,%6,%7}, {%8,%9}, {%0,%1,%2,%3};" \
                 : "+f"((d)[0]), "+f"((d)[1]), "+f"((d)[2]), "+f"((d)[3]) \
                 : "r"((a)[0]), "r"((a)[1]), "r"((a)[2]), "r"((a)[3]), \
                   "r"(b0r), "r"(b1r))

#define CPASYNC16(dst, src) \
    asm volatile("cp.async.cg.shared.global [%0], [%1], 16;" \
                 :: "r"(dst), "l"(src))
#define CPCOMMIT()  asm volatile("cp.async.commit_group;" ::: "memory")
#define CPWAIT(n)   asm volatile("cp.async.wait_group %0;" :: "n"(n) : "memory")

// XOR swizzle for 128B rows: chunk(0..7) ^= row&7 -> conflict-free ldmatrix
__device__ __forceinline__ uint32_t swz128(uint32_t o) {
    return o ^ (((o >> 7) & 7u) << 4);
}

__device__ __forceinline__ uint32_t packh(float a, float b) {
    __half x = __float2half(a), y = __float2half(b);
    return (uint32_t)__half_as_ushort(x) | ((uint32_t)__half_as_ushort(y) << 16);
}

__device__ __forceinline__ void trunc_store(void* hp, float4 v) {
    uint2 hu;
    hu.x = packh(v.x, v.y);
    hu.y = packh(v.z, v.w);
    *reinterpret_cast<uint2*>(hp) = hu;
}

// 2^y via FMA-pipe polynomial (no MUFU)
__device__ __forceinline__ float exp2p(float y) {
    y = fmaxf(y, -120.f);
    float t = y + 12582912.f;
    int   n = (__float_as_int(t) & 0x7FFFFF) - 0x400000;
    float f = y - (t - 12582912.f);
    float p = 1.3333558146e-3f;
    p = fmaf(p, f, 9.6181291076e-3f);
    p = fmaf(p, f, 5.5504108664e-2f);
    p = fmaf(p, f, 2.4022650695e-1f);
    p = fmaf(p, f, 6.9314718056e-1f);
    p = fmaf(p, f, 1.0f);
    return __int_as_float(__float_as_int(p) + (n << 23));
}

// ---------------------------------------------------------------------------
// Pre-truncate helpers
// ---------------------------------------------------------------------------
__global__ void trunc_plain(const float4* __restrict__ in, __half* __restrict__ h) {
    size_t i = (size_t)blockIdx.x * 256 + threadIdx.x;
    trunc_store(h + 4 * i, in[i]);
}

__global__ void trans_trunc(const float* __restrict__ in, __half* __restrict__ oh) {
    __shared__ float t[32][33];
    int bx = blockIdx.x * 32, by = blockIdx.y * 32;
    #pragma unroll
    for (int i = 0; i < 32; i += 8)
        t[threadIdx.y + i][threadIdx.x] = in[(size_t)(by + threadIdx.y + i) * DMODEL + bx + threadIdx.x];
    __syncthreads();
    #pragma unroll
    for (int i = 0; i < 32; i += 8) {
        float v = t[threadIdx.x][threadIdx.y + i];
        oh[(size_t)(bx + threadIdx.y + i) * DMODEL + by + threadIdx.x] = __float2half(v);
    }
}

// ---------------------------------------------------------------------------
// Single-fp16 mma.sync GEMM: C[m,n] = sum_k A[m,k]*B[n,k].
// Tile 128x128, BK=64, warp 32x64, 3-stage cp.async, 128B-row swizzle, 2 CTA/SM.
// EPI: 0=fp32 C; 1=three scaled fp16; 2=one scaled fp16; 4=plain fp16.
// ---------------------------------------------------------------------------
static constexpr int STAGE_B  = 32768;
static constexpr int SMEM_DYN = 3 * STAGE_B;     // 98304

template<int EPI>
__global__ __launch_bounds__(256, 2)
void gemm_fp16(const __half* __restrict__ Ah, const __half* __restrict__ Bh,
               float* __restrict__ C,
               const float* __restrict__ s0, const float* __restrict__ s1,
               const float* __restrict__ s2,
               __half* __restrict__ P0, __half* __restrict__ P1,
               __half* __restrict__ P2)
{
    extern __shared__ char smem[];
    const int tid  = threadIdx.x;
    const int lane = tid & 31;
    const int wid  = tid >> 5;
    const int bm   = blockIdx.y * 128;
    const int bn   = blockIdx.x * 128;
    const int wm0  = (wid & 3) * 32;
    const int wn0  = (wid >> 2) * 64;
    const uint32_t sbase = smem_u32(smem);

    const int arow = tid >> 1;                  // 0..127
    const int acol = (tid & 1) * 4;             // chunk base 0 or 4

    const char* gA = (const char*)Ah + (size_t)(bm + arow) * 2048 + acol * 16;
    const char* gB = (const char*)Bh + (size_t)(bn + arow) * 2048 + acol * 16;
    uint32_t soA[4];
    #pragma unroll
    for (int i = 0; i < 4; ++i)
        soA[i] = swz128((uint32_t)(arow * 128 + (acol + i) * 16));

    auto issue_stage = [&](int c, int s) {
        const size_t k0b = (size_t)c * 128;
        const uint32_t st = sbase + (uint32_t)s * STAGE_B;
        #pragma unroll
        for (int i = 0; i < 4; ++i)
            CPASYNC16(st + soA[i], gA + k0b + i * 16);
        #pragma unroll
        for (int i = 0; i < 4; ++i)
            CPASYNC16(st + 16384u + soA[i], gB + k0b + i * 16);
        CPCOMMIT();
    };

    float acc[2][8][4];
    #pragma unroll
    for (int i = 0; i < 2; ++i)
        #pragma unroll
        for (int j = 0; j < 8; ++j)
            #pragma unroll
            for (int q = 0; q < 4; ++q) acc[i][j][q] = 0.f;

    uint32_t aoff[2], boff[4];
    #pragma unroll
    for (int mt = 0; mt < 2; ++mt)
        aoff[mt] = (uint32_t)((wm0 + mt * 16 + (lane & 15)) * 128 + ((lane >> 4) << 4));
    #pragma unroll
    for (int bb = 0; bb < 4; ++bb)
        boff[bb] = (uint32_t)((wn0 + bb * 16 + (lane & 7) + ((lane >> 4) << 3)) * 128 + ((lane & 8) << 1));

    auto compute = [&](int s) {
        const uint32_t st = sbase + (uint32_t)s * STAGE_B;
        #pragma unroll
        for (int ks = 0; ks < 4; ++ks) {
            const uint32_t kb = ks * 32u;
            uint32_t af[2][4], bf[4][4];
            #pragma unroll
            for (int mt = 0; mt < 2; ++mt)
                LDMX4(af[mt][0], af[mt][1], af[mt][2], af[mt][3],
                      st + swz128(aoff[mt] + kb));
            #pragma unroll
            for (int bb = 0; bb < 4; ++bb)
                LDMX4(bf[bb][0], bf[bb][1], bf[bb][2], bf[bb][3],
                      st + 16384u + swz128(boff[bb] + kb));
            #pragma unroll
            for (int bb = 0; bb < 4; ++bb)
                #pragma unroll
                for (int mt = 0; mt < 2; ++mt) {
                    MMA16816_2(acc[mt][2 * bb],     af[mt], bf[bb][0], bf[bb][1]);
                    MMA16816_2(acc[mt][2 * bb + 1], af[mt], bf[bb][2], bf[bb][3]);
                }
        }
    };

    issue_stage(0, 0);
    issue_stage(1, 1);

    for (int c = 0; c < 16; ++c) {
        if (c < 15) { CPWAIT(1); } else { CPWAIT(0); }
        __syncthreads();
        if (c + 2 < 16) issue_stage(c + 2, (c + 2) % 3);
        compute(c % 3);
    }

    // ---- epilogue
    #pragma unroll
    for (int mt = 0; mt < 2; ++mt) {
        const int m = bm + wm0 + mt * 16 + (lane >> 2);
        #pragma unroll
        for (int nf = 0; nf < 8; ++nf) {
            const int n = bn + wn0 + nf * 8 + (lane & 3) * 2;
            const size_t o0 = (size_t)m * DMODEL + n;
            const size_t o1 = (size_t)(m + 8) * DMODEL + n;
            if (EPI == 0) {
                float2 v0 = {acc[mt][nf][0], acc[mt][nf][1]};
                float2 v1 = {acc[mt][nf][2], acc[mt][nf][3]};
                *reinterpret_cast<float2*>(C + o0) = v0;
                *reinterpret_cast<float2*>(C + o1) = v1;
            } else if (EPI == 4) {
                *reinterpret_cast<uint32_t*>(P0 + o0) = packh(acc[mt][nf][0], acc[mt][nf][1]);
                *reinterpret_cast<uint32_t*>(P0 + o1) = packh(acc[mt][nf][2], acc[mt][nf][3]);
            } else {
                float2 sc0 = *reinterpret_cast<const float2*>(s0 + n);
                *reinterpret_cast<uint32_t*>(P0 + o0) = packh(acc[mt][nf][0] * sc0.x, acc[mt][nf][1] * sc0.y);
                *reinterpret_cast<uint32_t*>(P0 + o1) = packh(acc[mt][nf][2] * sc0.x, acc[mt][nf][3] * sc0.y);
                if (EPI == 1) {
                    float2 sc1 = *reinterpret_cast<const float2*>(s1 + n);
                    float2 sc2 = *reinterpret_cast<const float2*>(s2 + n);
                    *reinterpret_cast<uint32_t*>(P1 + o0) = packh(acc[mt][nf][0] * sc1.x, acc[mt][nf][1] * sc1.y);
                    *reinterpret_cast<uint32_t*>(P1 + o1) = packh(acc[mt][nf][2] * sc1.x, acc[mt][nf][3] * sc1.y);
                    *reinterpret_cast<uint32_t*>(P2 + o0) = packh(acc[mt][nf][0] * sc2.x, acc[mt][nf][1] * sc2.y);
                    *reinterpret_cast<uint32_t*>(P2 + o1) = packh(acc[mt][nf][2] * sc2.x, acc[mt][nf][3] * sc2.y);
                }
            }
        }
    }
}

// ---------------------------------------------------------------------------
// fp16 flash attention: Q/K/V/P all single fp16. 2 CTAs/SM (cross-CTA latency
// hiding). Bias loaded inline in scale step (keeps regs <= 128, no spills).
// K/V via 3-stage cp.async; Q copied smem-direct once.
// ---------------------------------------------------------------------------
static constexpr int RSA    = 72;
static constexpr int QMAT_E = 128 * RSA;           // 9216
static constexpr int STG_E  = 2 * 64 * RSA;        // 9216
static constexpr int ASMEM  = (QMAT_E + 3 * STG_E) * 2;   // 73728 bytes

__global__ __launch_bounds__(256, 2)
void attn_mma(const __half* __restrict__ Qh,
              const __half* __restrict__ Kh, const __half* __restrict__ Vh,
              const float* __restrict__ bias,
              __half* __restrict__ AOh)
{
    extern __shared__ __half asmem[];
    const int tid  = threadIdx.x;
    const int lane = tid & 31;
    const int w    = tid >> 5;
    const int qt   = (int)gridDim.x - 1 - (int)blockIdx.x;   // heavy first
    const int h    = blockIdx.y;
    const int b    = blockIdx.z;
    const int q0   = qt * 128;
    const uint32_t sbase = smem_u32(asmem);
    const int nt   = 2 * qt + 2;

    const int krow = tid >> 2;
    const int kseg = (tid & 3) * 32;
    const char* gK = (const char*)(Kh + (size_t)(b * SEQ + krow) * DMODEL + h * DHEAD) + kseg;
    const char* gV = (const char*)(Vh + (size_t)(b * SEQ + krow) * DMODEL + h * DHEAD) + kseg;
    const uint32_t kvoff = (uint32_t)(krow * 144 + kseg);

    auto issue_kv = [&](int kt, int s) {
        const size_t gofs = (size_t)kt * 64 * 2048;
        const uint32_t st = sbase + (uint32_t)(QMAT_E + s * STG_E) * 2;
        CPASYNC16(st + kvoff,              gK + gofs);
        CPASYNC16(st + kvoff + 16,         gK + gofs + 16);
        CPASYNC16(st + 9216u + kvoff,      gV + gofs);
        CPASYNC16(st + 9216u + kvoff + 16, gV + gofs + 16);
        CPCOMMIT();
    };

    issue_kv(0, 0);
    issue_kv(1, 1);

    // ---- copy Q gmem->smem (16B chunks)
    {
        const __half* Qb = Qh + (size_t)(b * SEQ + q0) * DMODEL + h * DHEAD;
        #pragma unroll
        for (int i = 0; i < 4; ++i) {
            int idx = tid + i * 256;             // 0..1023
            int r   = idx >> 3;
            int c16 = idx & 7;
            uint4 v = *reinterpret_cast<const uint4*>(Qb + (size_t)r * DMODEL + c16 * 8);
            *reinterpret_cast<uint4*>(asmem + r * RSA + c16 * 8) = v;
        }
    }
    __syncthreads();

    uint32_t qf[4][4];
    #pragma unroll
    for (int ks = 0; ks < 4; ++ks) {
        const uint32_t off = ((w * 16 + (lane & 15)) * RSA + ks * 16 + ((lane >> 4) << 3)) * 2;
        LDMX4(qf[ks][0], qf[ks][1], qf[ks][2], qf[ks][3], sbase + off);
    }

    float m0 = -1e30f, m1 = -1e30f, l0 = 0.f, l1 = 0.f;
    float o[8][4];
    #pragma unroll
    for (int j = 0; j < 8; ++j)
        #pragma unroll
        for (int q = 0; q < 4; ++q) o[j][q] = 0.f;

    const int q_r0 = q0 + w * 16 + (lane >> 2);
    const int q_r1 = q_r0 + 8;
    const float* bph = bias + (size_t)h * SEQ * SEQ;

    for (int kt = 0; kt < nt; ++kt) {
        const int k0 = kt * 64;
        if (kt + 1 < nt) { CPWAIT(1); } else { CPWAIT(0); }
        __syncthreads();
        if (kt + 2 < nt) issue_kv(kt + 2, (kt + 2) % 3);

        const uint32_t Khu = sbase + (uint32_t)(QMAT_E + (kt % 3) * STG_E) * 2;
        const uint32_t Vhu = Khu + 9216u;

        // ---- S = Q K^T (single)
        float sacc[8][4];
        #pragma unroll
        for (int j = 0; j < 8; ++j)
            #pragma unroll
            for (int q = 0; q < 4; ++q) sacc[j][q] = 0.f;
        #pragma unroll
        for (int ks = 0; ks < 4; ++ks) {
            #pragma unroll
            for (int bb = 0; bb < 4; ++bb) {
                const uint32_t off =
                    ((bb * 16 + (lane & 7) + ((lane >> 4) << 3)) * RSA + ks * 16 + (lane & 8)) * 2;
                uint32_t b0, b1, b2, b3;
                LDMX4(b0, b1, b2, b3, Khu + off);
                MMA16816_2(sacc[2 * bb],     qf[ks], b0, b1);
                MMA16816_2(sacc[2 * bb + 1], qf[ks], b2, b3);
            }
        }

        // ---- scale + bias (log2 domain) + causal mask (bias loaded inline)
        const bool mask = (kt >= 2 * qt);
        const float* r0p = bph + (size_t)q_r0 * SEQ + k0 + 2 * (lane & 3);
        const float* r1p = bph + (size_t)q_r1 * SEQ + k0 + 2 * (lane & 3);
        #pragma unroll
        for (int nf = 0; nf < 8; ++nf) {
            float2 b0 = *reinterpret_cast<const float2*>(r0p + nf * 8);
            float2 b1 = *reinterpret_cast<const float2*>(r1p + nf * 8);
            float v0 = fmaf(sacc[nf][0], 0.18033688f, b0.x * 1.4426950f);
            float v1 = fmaf(sacc[nf][1], 0.18033688f, b0.y * 1.4426950f);
            float v2 = fmaf(sacc[nf][2], 0.18033688f, b1.x * 1.4426950f);
            float v3 = fmaf(sacc[nf][3], 0.18033688f, b1.y * 1.4426950f);
            if (mask) {
                const int kc = k0 + nf * 8 + 2 * (lane & 3);
                if (kc     > q_r0) v0 = -1e30f;
                if (kc + 1 > q_r0) v1 = -1e30f;
                if (kc     > q_r1) v2 = -1e30f;
                if (kc + 1 > q_r1) v3 = -1e30f;
            }
            sacc[nf][0] = v0; sacc[nf][1] = v1; sacc[nf][2] = v2; sacc[nf][3] = v3;
        }

        // ---- online softmax (base 2)
        float m0n = m0, m1n = m1;
        #pragma unroll
        for (int nf = 0; nf < 8; ++nf) {
            m0n = fmaxf(m0n, fmaxf(sacc[nf][0], sacc[nf][1]));
            m1n = fmaxf(m1n, fmaxf(sacc[nf][2], sacc[nf][3]));
        }
        m0n = fmaxf(m0n, __shfl_xor_sync(0xffffffffu, m0n, 1));
        m0n = fmaxf(m0n, __shfl_xor_sync(0xffffffffu, m0n, 2));
        m1n = fmaxf(m1n, __shfl_xor_sync(0xffffffffu, m1n, 1));
        m1n = fmaxf(m1n, __shfl_xor_sync(0xffffffffu, m1n, 2));
        const float c0 = exp2p(m0 - m0n), c1 = exp2p(m1 - m1n);
        m0 = m0n; m1 = m1n;
        l0 *= c0;  l1 *= c1;
        #pragma unroll
        for (int nf = 0; nf < 8; ++nf) {
            o[nf][0] *= c0; o[nf][1] *= c0;
            o[nf][2] *= c1; o[nf][3] *= c1;
        }

        uint32_t pA0[8], pA1[8];
        #pragma unroll
        for (int nf = 0; nf < 8; ++nf) {
            float p0 = exp2p(sacc[nf][0] - m0);
            float p1 = exp2p(sacc[nf][1] - m0);
            float p2 = exp2p(sacc[nf][2] - m1);
            float p3 = exp2p(sacc[nf][3] - m1);
            l0 += p0 + p1; l1 += p2 + p3;
            pA0[nf] = packh(p0, p1);
            pA1[nf] = packh(p2, p3);
        }

        // ---- O += P V (single, V via ldmatrix.trans)
        #pragma unroll
        for (int ks = 0; ks < 4; ++ks) {
            uint32_t ah[4] = { pA0[2 * ks], pA1[2 * ks], pA0[2 * ks + 1], pA1[2 * ks + 1] };
            #pragma unroll
            for (int ng = 0; ng < 4; ++ng) {
                const uint32_t off =
                    ((ks * 16 + (lane & 7) + (lane & 8)) * RSA + ng * 16 + ((lane >> 4) << 3)) * 2;
                uint32_t h0, h1, h2, h3;
                LDMX4T(h0, h1, h2, h3, Vhu + off);
                MMA16816_2(o[2 * ng],     ah, h0, h1);
                MMA16816_2(o[2 * ng + 1], ah, h2, h3);
            }
        }
    }

    l0 += __shfl_xor_sync(0xffffffffu, l0, 1);
    l0 += __shfl_xor_sync(0xffffffffu, l0, 2);
    l1 += __shfl_xor_sync(0xffffffffu, l1, 1);
    l1 += __shfl_xor_sync(0xffffffffu, l1, 2);
    const float i0 = 1.f / l0, i1 = 1.f / l1;
    const size_t r0off = (size_t)(b * SEQ + q_r0) * DMODEL + h * DHEAD + 2 * (lane & 3);
    const size_t r1off = (size_t)(b * SEQ + q_r1) * DMODEL + h * DHEAD + 2 * (lane & 3);
    #pragma unroll
    for (int nf = 0; nf < 8; ++nf) {
        *reinterpret_cast<uint32_t*>(AOh + r0off + nf * 8) = packh(o[nf][0] * i0, o[nf][1] * i0);
        *reinterpret_cast<uint32_t*>(AOh + r1off + nf * 8) = packh(o[nf][2] * i1, o[nf][3] * i1);
    }
}

// ---------------------------------------------------------------------------
extern "C" void kernel_launch(void* const* d_in, const int* in_sizes, int n_in,
                              void* d_out, int out_size)
{
    const float* x     = (const float*)d_in[0];
    const float* basis = (const float*)d_in[1];
    const float* sq    = (const float*)d_in[2];
    const float* sk    = (const float*)d_in[3];
    const float* sv    = (const float*)d_in[4];
    const float* so    = (const float*)d_in[5];
    const float* bias  = (const float*)d_in[6];
    float*       out   = (float*)d_out;

    __half *Xh, *BTh, *Bmh, *XB3, *QKV, *AOh, *O1h;
    cudaGetSymbolAddress((void**)&Xh,  g_Xh);
    cudaGetSymbolAddress((void**)&BTh, g_BTh);
    cudaGetSymbolAddress((void**)&Bmh, g_Bmh);
    cudaGetSymbolAddress((void**)&XB3, g_XB3);
    cudaGetSymbolAddress((void**)&QKV, g_QKV);
    cudaGetSymbolAddress((void**)&AOh, g_AOh);
    cudaGetSymbolAddress((void**)&O1h, g_O1h);

    const size_t SEG = (size_t)MROWS * DMODEL;
    __half* XBq = XB3;            __half* XBk = XB3 + SEG;  __half* XBv = XB3 + 2 * SEG;
    __half* Qh  = QKV;            __half* Kh  = QKV + SEG;  __half* Vh  = QKV + 2 * SEG;

    cudaFuncSetAttribute(gemm_fp16<0>, cudaFuncAttributeMaxDynamicSharedMemorySize, SMEM_DYN);
    cudaFuncSetAttribute(gemm_fp16<1>, cudaFuncAttributeMaxDynamicSharedMemorySize, SMEM_DYN);
    cudaFuncSetAttribute(gemm_fp16<2>, cudaFuncAttributeMaxDynamicSharedMemorySize, SMEM_DYN);
    cudaFuncSetAttribute(gemm_fp16<4>, cudaFuncAttributeMaxDynamicSharedMemorySize, SMEM_DYN);
    cudaFuncSetAttribute(attn_mma, cudaFuncAttributeMaxDynamicSharedMemorySize, ASMEM);

    // pre-truncate inputs
    trunc_plain<<<MROWS * DMODEL / 1024, 256>>>((const float4*)x, Xh);
    trunc_plain<<<DMODEL * DMODEL / 1024, 256>>>((const float4*)basis, Bmh);
    trans_trunc<<<dim3(32, 32), dim3(32, 8)>>>(basis, BTh);

    const dim3 gg(DMODEL / 128, MROWS / 128);
    // G1: XB = X @ basis, emits scale-fused singles for q/k/v
    gemm_fp16<1><<<gg, 256, SMEM_DYN>>>(Xh, BTh, nullptr, sq, sk, sv, XBq, XBk, XBv);
    // G2-4 merged: QKV = XB3 @ basis (batched along M: 12288 rows)
    const dim3 gqkv(DMODEL / 128, 3 * MROWS / 128);
    gemm_fp16<4><<<gqkv, 256, SMEM_DYN>>>(XB3, Bmh, nullptr, nullptr, nullptr, nullptr,
                                          QKV, nullptr, nullptr);

    attn_mma<<<dim3(SEQ / 128, NHEADS, BATCH), 256, ASMEM>>>(Qh, Kh, Vh, bias, AOh);

    // G5: O1 = AO @ basis, so-fused single
    gemm_fp16<2><<<gg, 256, SMEM_DYN>>>(AOh, BTh, nullptr, so, nullptr, nullptr,
                                        O1h, nullptr, nullptr);
    // G6: out = O1s @ basis^T, fp32
    gemm_fp16<0><<<gg, 256, SMEM_DYN>>>(O1h, Bmh, out, nullptr, nullptr, nullptr,
                                        nullptr, nullptr, nullptr);
}